// round 3
// baseline (speedup 1.0000x reference)
#include <cuda_runtime.h>
#include <math.h>

// ---------------------------------------------------------------------------
// Problem constants
//   B=4, S=2048, D=256, H=8, KD=256, FF=512, M = B*S = 8192, HKD = H*KD = 2048
// ---------------------------------------------------------------------------
#define MB   4
#define SS   2048
#define DD   256
#define HH   8
#define KDD  256
#define FFD  512
#define MTOK (MB * SS)        // 8192
#define HKD  (HH * KDD)       // 2048
#define BH   (MB * HH)        // 32

// ---------------------------------------------------------------------------
// Static scratch (device .bss — allowed; no runtime allocation)
// ---------------------------------------------------------------------------
__device__ float g_q[(long long)MTOK * HKD];          //  64 MB [b,s,h,e]
__device__ float g_k[(long long)MTOK * HKD];          //  64 MB
__device__ float g_v[(long long)MTOK * HKD];          //  64 MB
__device__ float g_sc[(long long)BH * SS * SS];       // 512 MB [b,h,q,k]
__device__ float g_at[(long long)MTOK * HKD];         //  64 MB [b,s,h,e]
__device__ float g_ao[(long long)MTOK * DD];          //   8 MB
__device__ float g_z [(long long)MTOK * DD];          //   8 MB
__device__ float g_h [(long long)MTOK * FFD];         //  16 MB
__device__ float g_f [(long long)MTOK * DD];          //   8 MB

// ---------------------------------------------------------------------------
// Generic batched SGEMM: C = alpha * (A @ B(^T) + bias) , optional relu.
// Tiles: 128x128x8, 256 threads, 8x8 per-thread microtile.
// All dims assumed multiples of tile sizes (true for every call here).
// Batch z decomposes as (zo = z / batch_div, zi = z % batch_div) with
// independent outer/inner strides per operand — this lets one kernel cover
// plain GEMMs, per-(b,h) attention GEMMs, and [b,s,h,e] layouts.
// ---------------------------------------------------------------------------
#define BM 128
#define BN 128
#define BK 8

template <bool TRANS_B>
__global__ void __launch_bounds__(256)
gemm_kernel(const float* __restrict__ A, const float* __restrict__ B,
            float* __restrict__ C, const float* __restrict__ bias,
            int K, int lda, int ldb, int ldc,
            int batch_div,
            long long sAo, long long sAi,
            long long sBo, long long sBi,
            long long sCo, long long sCi,
            float alpha, int relu)
{
    const int z  = blockIdx.z;
    const int zo = z / batch_div;
    const int zi = z - zo * batch_div;
    A += zo * sAo + zi * sAi;
    B += zo * sBo + zi * sBi;
    C += zo * sCo + zi * sCi;

    __shared__ float As[BK][BM];
    __shared__ float Bs[BK][BN + 4];

    const int tid  = threadIdx.x;
    const int m0   = blockIdx.y * BM;
    const int n0   = blockIdx.x * BN;
    const int row0 = (tid >> 4) << 3;   // 0..120
    const int col0 = (tid & 15) << 3;   // 0..120

    float acc[8][8];
#pragma unroll
    for (int i = 0; i < 8; i++)
#pragma unroll
        for (int j = 0; j < 8; j++) acc[i][j] = 0.f;

    const int aRow = tid >> 1;          // 0..127
    const int aCol = (tid & 1) * 4;     // 0 or 4
    const int bRow = tid >> 5;          // 0..7   (NN path)
    const int bCol = (tid & 31) * 4;    // 0..124 (NN path)

    for (int k0 = 0; k0 < K; k0 += BK) {
        // A tile: BM x BK, store transposed As[k][m]
        float4 av = *(const float4*)(A + (long long)(m0 + aRow) * lda + k0 + aCol);
        As[aCol + 0][aRow] = av.x;
        As[aCol + 1][aRow] = av.y;
        As[aCol + 2][aRow] = av.z;
        As[aCol + 3][aRow] = av.w;

        if (!TRANS_B) {
            // B is K x N row-major
            float4 bv = *(const float4*)(B + (long long)(k0 + bRow) * ldb + n0 + bCol);
            *(float4*)&Bs[bRow][bCol] = bv;
        } else {
            // B is N x K row-major (B^T): Bs[k][n] = B[n][k]
            float4 bv = *(const float4*)(B + (long long)(n0 + aRow) * ldb + k0 + aCol);
            Bs[aCol + 0][aRow] = bv.x;
            Bs[aCol + 1][aRow] = bv.y;
            Bs[aCol + 2][aRow] = bv.z;
            Bs[aCol + 3][aRow] = bv.w;
        }
        __syncthreads();

#pragma unroll
        for (int kk = 0; kk < BK; kk++) {
            float4 a0 = *(const float4*)&As[kk][row0];
            float4 a1 = *(const float4*)&As[kk][row0 + 4];
            float4 b0 = *(const float4*)&Bs[kk][col0];
            float4 b1 = *(const float4*)&Bs[kk][col0 + 4];
            float a[8] = {a0.x, a0.y, a0.z, a0.w, a1.x, a1.y, a1.z, a1.w};
            float b[8] = {b0.x, b0.y, b0.z, b0.w, b1.x, b1.y, b1.z, b1.w};
#pragma unroll
            for (int i = 0; i < 8; i++)
#pragma unroll
                for (int j = 0; j < 8; j++)
                    acc[i][j] += a[i] * b[j];
        }
        __syncthreads();
    }

#pragma unroll
    for (int i = 0; i < 8; i++) {
        const long long base = (long long)(m0 + row0 + i) * ldc + n0 + col0;
#pragma unroll
        for (int j = 0; j < 8; j++) {
            float vv = acc[i][j];
            if (bias) vv += bias[n0 + col0 + j];
            vv *= alpha;
            if (relu) vv = fmaxf(vv, 0.f);
            C[base + j] = vv;
        }
    }
}

// ---------------------------------------------------------------------------
// Row softmax over rows of length 2048 (one block per row; registers-resident)
// ---------------------------------------------------------------------------
__global__ void __launch_bounds__(256)
softmax_kernel(float* __restrict__ s)
{
    float* row = s + (long long)blockIdx.x * SS;
    const int t = threadIdx.x;
    float v[8];
#pragma unroll
    for (int i = 0; i < 8; i++) v[i] = row[t + i * 256];

    float m = v[0];
#pragma unroll
    for (int i = 1; i < 8; i++) m = fmaxf(m, v[i]);

    __shared__ float sh[256];
    sh[t] = m; __syncthreads();
    for (int st = 128; st; st >>= 1) {
        if (t < st) sh[t] = fmaxf(sh[t], sh[t + st]);
        __syncthreads();
    }
    m = sh[0]; __syncthreads();

    float sum = 0.f;
#pragma unroll
    for (int i = 0; i < 8; i++) { v[i] = expf(v[i] - m); sum += v[i]; }

    sh[t] = sum; __syncthreads();
    for (int st = 128; st; st >>= 1) {
        if (t < st) sh[t] += sh[t + st];
        __syncthreads();
    }
    const float inv = 1.f / sh[0];
#pragma unroll
    for (int i = 0; i < 8; i++) row[t + i * 256] = v[i] * inv;
}

// ---------------------------------------------------------------------------
// LayerNorm (+ residual). D = 256 = blockDim.
//   add_before = 0 :  out = LN(a)*g + b + r     (attention branch)
//   add_before = 1 :  out = LN(a + r)*g + b     (final LN)
// Keras eps = 1e-3 added to variance.
// ---------------------------------------------------------------------------
__global__ void __launch_bounds__(256)
ln_kernel(const float* __restrict__ a, const float* __restrict__ r,
          const float* __restrict__ g, const float* __restrict__ b,
          float* __restrict__ out, int add_before)
{
    const int t = threadIdx.x;
    const long long base = (long long)blockIdx.x * DD;
    const float av = a[base + t];
    const float rv = r[base + t];
    const float val = add_before ? (av + rv) : av;

    __shared__ float sh[256];
    sh[t] = val; __syncthreads();
    for (int st = 128; st; st >>= 1) {
        if (t < st) sh[t] += sh[t + st];
        __syncthreads();
    }
    const float mean = sh[0] * (1.f / 256.f);
    __syncthreads();

    const float d = val - mean;
    sh[t] = d * d; __syncthreads();
    for (int st = 128; st; st >>= 1) {
        if (t < st) sh[t] += sh[t + st];
        __syncthreads();
    }
    const float var = sh[0] * (1.f / 256.f);

    const float y = d * rsqrtf(var + 1e-3f) * g[t] + b[t];
    out[base + t] = add_before ? y : (y + rv);
}

// ---------------------------------------------------------------------------
// Launch: 11 kernels, all on the default (capture) stream.
// ---------------------------------------------------------------------------
extern "C" void kernel_launch(void* const* d_in, const int* in_sizes, int n_in,
                              void* d_out, int out_size)
{
    const float* x   = (const float*)d_in[0];
    const float* Wq  = (const float*)d_in[1];
    const float* bq  = (const float*)d_in[2];
    const float* Wk  = (const float*)d_in[3];
    const float* bk  = (const float*)d_in[4];
    const float* Wv  = (const float*)d_in[5];
    const float* bv  = (const float*)d_in[6];
    const float* Wo  = (const float*)d_in[7];
    const float* bo  = (const float*)d_in[8];
    const float* g1  = (const float*)d_in[9];
    const float* be1 = (const float*)d_in[10];
    const float* W1  = (const float*)d_in[11];
    const float* bb1 = (const float*)d_in[12];
    const float* W2  = (const float*)d_in[13];
    const float* bb2 = (const float*)d_in[14];
    const float* g2  = (const float*)d_in[15];
    const float* be2 = (const float*)d_in[16];
    float* out = (float*)d_out;

    float *q, *k, *v, *sc, *at, *ao, *zz, *hh, *ff;
    cudaGetSymbolAddress((void**)&q,  g_q);
    cudaGetSymbolAddress((void**)&k,  g_k);
    cudaGetSymbolAddress((void**)&v,  g_v);
    cudaGetSymbolAddress((void**)&sc, g_sc);
    cudaGetSymbolAddress((void**)&at, g_at);
    cudaGetSymbolAddress((void**)&ao, g_ao);
    cudaGetSymbolAddress((void**)&zz, g_z);
    cudaGetSymbolAddress((void**)&hh, g_h);
    cudaGetSymbolAddress((void**)&ff, g_f);

    const dim3 blk(256);
    const float qscale = 1.0f / 16.0f;   // 1/sqrt(KD)

    // ---- Q/K/V projections: [8192,256] x [256,2048] -> [b,s,h,e] -----------
    {
        dim3 grid(HKD / BN, MTOK / BM, 1);
        gemm_kernel<false><<<grid, blk>>>(x, Wq, q, bq, DD, DD, HKD, HKD,
                                          1, 0, 0, 0, 0, 0, 0, qscale, 0);
        gemm_kernel<false><<<grid, blk>>>(x, Wk, k, bk, DD, DD, HKD, HKD,
                                          1, 0, 0, 0, 0, 0, 0, 1.f, 0);
        gemm_kernel<false><<<grid, blk>>>(x, Wv, v, bv, DD, DD, HKD, HKD,
                                          1, 0, 0, 0, 0, 0, 0, 1.f, 0);
    }

    // ---- scores = Q K^T per (b,h): 32 x [2048,2048,256] ---------------------
    {
        dim3 grid(SS / BN, SS / BM, BH);
        gemm_kernel<true><<<grid, blk>>>(q, k, sc, nullptr, KDD,
                                         HKD, HKD, SS,
                                         HH,
                                         (long long)SS * HKD, (long long)KDD,
                                         (long long)SS * HKD, (long long)KDD,
                                         (long long)HH * SS * SS, (long long)SS * SS,
                                         1.f, 0);
    }

    // ---- softmax over last axis --------------------------------------------
    softmax_kernel<<<BH * SS, blk>>>(sc);

    // ---- attn = P V per (b,h): 32 x [2048,256,2048] -> [b,s,h,e] ------------
    {
        dim3 grid(KDD / BN, SS / BM, BH);
        gemm_kernel<false><<<grid, blk>>>(sc, v, at, nullptr, SS,
                                          SS, HKD, HKD,
                                          HH,
                                          (long long)HH * SS * SS, (long long)SS * SS,
                                          (long long)SS * HKD, (long long)KDD,
                                          (long long)SS * HKD, (long long)KDD,
                                          1.f, 0);
    }

    // ---- output projection: [8192,2048] x [2048,256] ------------------------
    {
        dim3 grid(DD / BN, MTOK / BM, 1);
        gemm_kernel<false><<<grid, blk>>>(at, Wo, ao, bo, HKD, HKD, DD, DD,
                                          1, 0, 0, 0, 0, 0, 0, 1.f, 0);
    }

    // ---- z = LN(attn_out) + x ----------------------------------------------
    ln_kernel<<<MTOK, blk>>>(ao, x, g1, be1, zz, 0);

    // ---- FFN ----------------------------------------------------------------
    {
        dim3 grid(FFD / BN, MTOK / BM, 1);
        gemm_kernel<false><<<grid, blk>>>(zz, W1, hh, bb1, DD, DD, FFD, FFD,
                                          1, 0, 0, 0, 0, 0, 0, 1.f, 1);
    }
    {
        dim3 grid(DD / BN, MTOK / BM, 1);
        gemm_kernel<false><<<grid, blk>>>(hh, W2, ff, bb2, FFD, FFD, DD, DD,
                                          1, 0, 0, 0, 0, 0, 0, 1.f, 0);
    }

    // ---- out = LN(f + z) ----------------------------------------------------
    ln_kernel<<<MTOK, blk>>>(ff, zz, g2, be2, out, 1);
}

// round 4
// speedup vs baseline: 2.9194x; 2.9194x over previous
#include <cuda_runtime.h>
#include <math.h>

// ---------------------------------------------------------------------------
// Problem constants
//   B=4, S=2048, D=256, H=8, KD=256, FF=512, M = B*S = 8192, HKD = H*KD = 2048
// ---------------------------------------------------------------------------
#define MB   4
#define SS   2048
#define DD   256
#define HH   8
#define KDD  256
#define FFD  512
#define MTOK (MB * SS)        // 8192
#define HKD  (HH * KDD)       // 2048
#define BH   (MB * HH)        // 32

// ---------------------------------------------------------------------------
// Static scratch (device .bss — allowed; no runtime allocation)
// ---------------------------------------------------------------------------
__device__ float g_q[(long long)MTOK * HKD];          //  64 MB [b,s,h,e]
__device__ float g_k[(long long)MTOK * HKD];          //  64 MB
__device__ float g_v[(long long)MTOK * HKD];          //  64 MB
__device__ float g_sc[(long long)BH * SS * SS];       // 512 MB [b,h,q,k]
__device__ float g_at[(long long)MTOK * HKD];         //  64 MB [b,s,h,e]
__device__ float g_ao[(long long)MTOK * DD];          //   8 MB
__device__ float g_z [(long long)MTOK * DD];          //   8 MB
__device__ float g_h [(long long)MTOK * FFD];         //  16 MB
__device__ float g_f [(long long)MTOK * DD];          //   8 MB

// ---------------------------------------------------------------------------
// tf32 helpers
// ---------------------------------------------------------------------------
__device__ __forceinline__ unsigned f2tf(float f) {
    unsigned u;
    asm("cvt.rna.tf32.f32 %0, %1;" : "=r"(u) : "f"(f));
    return u;
}

__device__ __forceinline__ void mma_tf32(
    float& c0, float& c1, float& c2, float& c3,
    unsigned a0, unsigned a1, unsigned a2, unsigned a3,
    unsigned b0, unsigned b1)
{
    asm volatile(
        "mma.sync.aligned.m16n8k8.row.col.f32.tf32.tf32.f32 "
        "{%0,%1,%2,%3}, {%4,%5,%6,%7}, {%8,%9}, {%0,%1,%2,%3};"
        : "+f"(c0), "+f"(c1), "+f"(c2), "+f"(c3)
        : "r"(a0), "r"(a1), "r"(a2), "r"(a3), "r"(b0), "r"(b1));
}

// ---------------------------------------------------------------------------
// Batched tf32 tensor-core GEMM: C = alpha * (A @ B(^T) + bias), optional relu.
// Block tile 128x128x32, 256 threads = 8 warps (2 along M x 4 along N),
// warp tile 64x32 via m16n8k8 (4 m-tiles x 4 n-tiles, fp32 accum).
// All dims are multiples of tile sizes for every call in this file.
// Batch z decomposes as (zo = z/batch_div, zi = z%batch_div) with independent
// outer/inner strides per operand (covers per-(b,h) attention + [b,s,h,e]).
// ---------------------------------------------------------------------------
#define BM 128
#define BN 128
#define BK 32

template <bool TRANS_B>
__global__ void __launch_bounds__(256)
mma_gemm(const float* __restrict__ A, const float* __restrict__ B,
         float* __restrict__ C, const float* __restrict__ bias,
         int K, int lda, int ldb, int ldc,
         int batch_div,
         long long sAo, long long sAi,
         long long sBo, long long sBi,
         long long sCo, long long sCi,
         float alpha, int relu)
{
    const int z  = blockIdx.z;
    const int zo = z / batch_div;
    const int zi = z - zo * batch_div;
    A += zo * sAo + zi * sAi;
    B += zo * sBo + zi * sBi;
    C += zo * sCo + zi * sCi;

    // A: [m][k] padded to 36 (36%32=4 -> fragment banks g*4+tg, conflict-free)
    __shared__ unsigned As[BM][36];
    // B-NN: [k][n] padded to 136 (136%32=8 -> banks tg*8+g, conflict-free)
    // B-TN: [n][k] padded to 36 (same pattern as A)
    constexpr int BROWS = TRANS_B ? BN : BK;
    constexpr int BPAD  = TRANS_B ? 36 : 136;
    __shared__ unsigned Bs[BROWS][BPAD];

    const int tid  = threadIdx.x;
    const int lane = tid & 31;
    const int wrp  = tid >> 5;
    const int m0   = blockIdx.y * BM;
    const int n0   = blockIdx.x * BN;

    const int wm = (wrp & 1) * 64;      // warp M offset within block tile
    const int wn = (wrp >> 1) * 32;     // warp N offset
    const int g  = lane >> 2;           // group 0..7
    const int tg = lane & 3;            // thread-in-group 0..3

    float acc[4][4][4];
#pragma unroll
    for (int mi = 0; mi < 4; mi++)
#pragma unroll
        for (int ni = 0; ni < 4; ni++)
#pragma unroll
            for (int r = 0; r < 4; r++) acc[mi][ni][r] = 0.f;

    for (int k0 = 0; k0 < K; k0 += BK) {
        // ---- load A tile (128x32), convert to tf32 ----
#pragma unroll
        for (int i = 0; i < 4; i++) {
            const int s   = tid + i * 256;          // 0..1023
            const int row = s >> 3;                 // 0..127
            const int cg  = (s & 7) * 4;            // 0..28
            float4 v = *(const float4*)(A + (long long)(m0 + row) * lda + k0 + cg);
            uint4 t = {f2tf(v.x), f2tf(v.y), f2tf(v.z), f2tf(v.w)};
            *(uint4*)&As[row][cg] = t;
        }
        // ---- load B tile ----
        if (!TRANS_B) {
#pragma unroll
            for (int i = 0; i < 4; i++) {
                const int s   = tid + i * 256;
                const int row = s >> 5;             // k 0..31
                const int cg  = (s & 31) * 4;       // n 0..124
                float4 v = *(const float4*)(B + (long long)(k0 + row) * ldb + n0 + cg);
                uint4 t = {f2tf(v.x), f2tf(v.y), f2tf(v.z), f2tf(v.w)};
                *(uint4*)&Bs[row][cg] = t;
            }
        } else {
#pragma unroll
            for (int i = 0; i < 4; i++) {
                const int s   = tid + i * 256;
                const int row = s >> 3;             // n 0..127
                const int cg  = (s & 7) * 4;        // k 0..28
                float4 v = *(const float4*)(B + (long long)(n0 + row) * ldb + k0 + cg);
                uint4 t = {f2tf(v.x), f2tf(v.y), f2tf(v.z), f2tf(v.w)};
                *(uint4*)&Bs[row][cg] = t;
            }
        }
        __syncthreads();

        // ---- 4 k-steps of 8 ----
#pragma unroll
        for (int ks = 0; ks < BK; ks += 8) {
            unsigned a[4][4];
#pragma unroll
            for (int mi = 0; mi < 4; mi++) {
                const int r = wm + mi * 16 + g;
                a[mi][0] = As[r    ][ks + tg];
                a[mi][1] = As[r + 8][ks + tg];
                a[mi][2] = As[r    ][ks + tg + 4];
                a[mi][3] = As[r + 8][ks + tg + 4];
            }
            unsigned b[4][2];
#pragma unroll
            for (int ni = 0; ni < 4; ni++) {
                const int n = wn + ni * 8 + g;
                if (!TRANS_B) {
                    b[ni][0] = Bs[ks + tg    ][n];
                    b[ni][1] = Bs[ks + tg + 4][n];
                } else {
                    b[ni][0] = Bs[n][ks + tg];
                    b[ni][1] = Bs[n][ks + tg + 4];
                }
            }
#pragma unroll
            for (int mi = 0; mi < 4; mi++)
#pragma unroll
                for (int ni = 0; ni < 4; ni++)
                    mma_tf32(acc[mi][ni][0], acc[mi][ni][1],
                             acc[mi][ni][2], acc[mi][ni][3],
                             a[mi][0], a[mi][1], a[mi][2], a[mi][3],
                             b[ni][0], b[ni][1]);
        }
        __syncthreads();
    }

    // ---- epilogue: bias / alpha / relu, float2 stores ----
#pragma unroll
    for (int mi = 0; mi < 4; mi++) {
        const int r0 = m0 + wm + mi * 16 + g;
#pragma unroll
        for (int ni = 0; ni < 4; ni++) {
            const int col = n0 + wn + ni * 8 + tg * 2;
            float v0 = acc[mi][ni][0], v1 = acc[mi][ni][1];
            float v2 = acc[mi][ni][2], v3 = acc[mi][ni][3];
            if (bias) {
                const float b0 = bias[col], b1 = bias[col + 1];
                v0 += b0; v1 += b1; v2 += b0; v3 += b1;
            }
            v0 *= alpha; v1 *= alpha; v2 *= alpha; v3 *= alpha;
            if (relu) {
                v0 = fmaxf(v0, 0.f); v1 = fmaxf(v1, 0.f);
                v2 = fmaxf(v2, 0.f); v3 = fmaxf(v3, 0.f);
            }
            *(float2*)(C + (long long)r0 * ldc + col)       = make_float2(v0, v1);
            *(float2*)(C + (long long)(r0 + 8) * ldc + col) = make_float2(v2, v3);
        }
    }
}

// ---------------------------------------------------------------------------
// Row softmax over rows of length 2048 (one block per row; registers-resident)
// ---------------------------------------------------------------------------
__global__ void __launch_bounds__(256)
softmax_kernel(float* __restrict__ s)
{
    float* row = s + (long long)blockIdx.x * SS;
    const int t = threadIdx.x;
    float v[8];
#pragma unroll
    for (int i = 0; i < 8; i++) v[i] = row[t + i * 256];

    float m = v[0];
#pragma unroll
    for (int i = 1; i < 8; i++) m = fmaxf(m, v[i]);

    __shared__ float sh[256];
    sh[t] = m; __syncthreads();
    for (int st = 128; st; st >>= 1) {
        if (t < st) sh[t] = fmaxf(sh[t], sh[t + st]);
        __syncthreads();
    }
    m = sh[0]; __syncthreads();

    float sum = 0.f;
#pragma unroll
    for (int i = 0; i < 8; i++) { v[i] = expf(v[i] - m); sum += v[i]; }

    sh[t] = sum; __syncthreads();
    for (int st = 128; st; st >>= 1) {
        if (t < st) sh[t] += sh[t + st];
        __syncthreads();
    }
    const float inv = 1.f / sh[0];
#pragma unroll
    for (int i = 0; i < 8; i++) row[t + i * 256] = v[i] * inv;
}

// ---------------------------------------------------------------------------
// LayerNorm (+ residual). D = 256 = blockDim.
//   add_before = 0 :  out = LN(a)*g + b + r     (attention branch)
//   add_before = 1 :  out = LN(a + r)*g + b     (final LN)
// ---------------------------------------------------------------------------
__global__ void __launch_bounds__(256)
ln_kernel(const float* __restrict__ a, const float* __restrict__ r,
          const float* __restrict__ g, const float* __restrict__ b,
          float* __restrict__ out, int add_before)
{
    const int t = threadIdx.x;
    const long long base = (long long)blockIdx.x * DD;
    const float av = a[base + t];
    const float rv = r[base + t];
    const float val = add_before ? (av + rv) : av;

    __shared__ float sh[256];
    sh[t] = val; __syncthreads();
    for (int st = 128; st; st >>= 1) {
        if (t < st) sh[t] += sh[t + st];
        __syncthreads();
    }
    const float mean = sh[0] * (1.f / 256.f);
    __syncthreads();

    const float d = val - mean;
    sh[t] = d * d; __syncthreads();
    for (int st = 128; st; st >>= 1) {
        if (t < st) sh[t] += sh[t + st];
        __syncthreads();
    }
    const float var = sh[0] * (1.f / 256.f);

    const float y = d * rsqrtf(var + 1e-3f) * g[t] + b[t];
    out[base + t] = add_before ? y : (y + rv);
}

// ---------------------------------------------------------------------------
// Launch: 11 kernels, all on the default (capture) stream.
// ---------------------------------------------------------------------------
extern "C" void kernel_launch(void* const* d_in, const int* in_sizes, int n_in,
                              void* d_out, int out_size)
{
    const float* x   = (const float*)d_in[0];
    const float* Wq  = (const float*)d_in[1];
    const float* bq  = (const float*)d_in[2];
    const float* Wk  = (const float*)d_in[3];
    const float* bk  = (const float*)d_in[4];
    const float* Wv  = (const float*)d_in[5];
    const float* bv  = (const float*)d_in[6];
    const float* Wo  = (const float*)d_in[7];
    const float* bo  = (const float*)d_in[8];
    const float* g1  = (const float*)d_in[9];
    const float* be1 = (const float*)d_in[10];
    const float* W1  = (const float*)d_in[11];
    const float* bb1 = (const float*)d_in[12];
    const float* W2  = (const float*)d_in[13];
    const float* bb2 = (const float*)d_in[14];
    const float* g2  = (const float*)d_in[15];
    const float* be2 = (const float*)d_in[16];
    float* out = (float*)d_out;

    float *q, *k, *v, *sc, *at, *ao, *zz, *hh, *ff;
    cudaGetSymbolAddress((void**)&q,  g_q);
    cudaGetSymbolAddress((void**)&k,  g_k);
    cudaGetSymbolAddress((void**)&v,  g_v);
    cudaGetSymbolAddress((void**)&sc, g_sc);
    cudaGetSymbolAddress((void**)&at, g_at);
    cudaGetSymbolAddress((void**)&ao, g_ao);
    cudaGetSymbolAddress((void**)&zz, g_z);
    cudaGetSymbolAddress((void**)&hh, g_h);
    cudaGetSymbolAddress((void**)&ff, g_f);

    const dim3 blk(256);
    const float qscale = 1.0f / 16.0f;   // 1/sqrt(KD)

    // ---- Q/K/V projections: [8192,256] x [256,2048] -> [b,s,h,e] -----------
    {
        dim3 grid(HKD / BN, MTOK / BM, 1);
        mma_gemm<false><<<grid, blk>>>(x, Wq, q, bq, DD, DD, HKD, HKD,
                                       1, 0, 0, 0, 0, 0, 0, qscale, 0);
        mma_gemm<false><<<grid, blk>>>(x, Wk, k, bk, DD, DD, HKD, HKD,
                                       1, 0, 0, 0, 0, 0, 0, 1.f, 0);
        mma_gemm<false><<<grid, blk>>>(x, Wv, v, bv, DD, DD, HKD, HKD,
                                       1, 0, 0, 0, 0, 0, 0, 1.f, 0);
    }

    // ---- scores = Q K^T per (b,h): 32 x [2048,2048,256] ---------------------
    {
        dim3 grid(SS / BN, SS / BM, BH);
        mma_gemm<true><<<grid, blk>>>(q, k, sc, nullptr, KDD,
                                      HKD, HKD, SS,
                                      HH,
                                      (long long)SS * HKD, (long long)KDD,
                                      (long long)SS * HKD, (long long)KDD,
                                      (long long)HH * SS * SS, (long long)SS * SS,
                                      1.f, 0);
    }

    // ---- softmax over last axis --------------------------------------------
    softmax_kernel<<<BH * SS, blk>>>(sc);

    // ---- attn = P V per (b,h): 32 x [2048,256,2048] -> [b,s,h,e] ------------
    {
        dim3 grid(KDD / BN, SS / BM, BH);
        mma_gemm<false><<<grid, blk>>>(sc, v, at, nullptr, SS,
                                       SS, HKD, HKD,
                                       HH,
                                       (long long)HH * SS * SS, (long long)SS * SS,
                                       (long long)SS * HKD, (long long)KDD,
                                       (long long)SS * HKD, (long long)KDD,
                                       1.f, 0);
    }

    // ---- output projection: [8192,2048] x [2048,256] ------------------------
    {
        dim3 grid(DD / BN, MTOK / BM, 1);
        mma_gemm<false><<<grid, blk>>>(at, Wo, ao, bo, HKD, HKD, DD, DD,
                                       1, 0, 0, 0, 0, 0, 0, 1.f, 0);
    }

    // ---- z = LN(attn_out) + x ----------------------------------------------
    ln_kernel<<<MTOK, blk>>>(ao, x, g1, be1, zz, 0);

    // ---- FFN ----------------------------------------------------------------
    {
        dim3 grid(FFD / BN, MTOK / BM, 1);
        mma_gemm<false><<<grid, blk>>>(zz, W1, hh, bb1, DD, DD, FFD, FFD,
                                       1, 0, 0, 0, 0, 0, 0, 1.f, 1);
    }
    {
        dim3 grid(DD / BN, MTOK / BM, 1);
        mma_gemm<false><<<grid, blk>>>(hh, W2, ff, bb2, FFD, FFD, DD, DD,
                                       1, 0, 0, 0, 0, 0, 0, 1.f, 0);
    }

    // ---- out = LN(f + z) ----------------------------------------------------
    ln_kernel<<<MTOK, blk>>>(ff, zz, g2, be2, out, 1);
}

// round 5
// speedup vs baseline: 3.2909x; 1.1273x over previous
#include <cuda_runtime.h>
#include <math.h>

// ---------------------------------------------------------------------------
// Problem constants
//   B=4, S=2048, D=256, H=8, KD=256, FF=512, M = B*S = 8192, HKD = H*KD = 2048
// ---------------------------------------------------------------------------
#define MB   4
#define SS   2048
#define DD   256
#define HH   8
#define KDD  256
#define FFD  512
#define MTOK (MB * SS)        // 8192
#define HKD  (HH * KDD)       // 2048
#define BH   (MB * HH)        // 32

// ---------------------------------------------------------------------------
// Static scratch (device .bss — allowed; no runtime allocation)
// All GEMM operands hold tf32 bit patterns (converted by producers).
// ---------------------------------------------------------------------------
__device__ float g_q[(long long)MTOK * HKD];          //  64 MB [b,s,h,e] (tf32)
__device__ float g_k[(long long)MTOK * HKD];          //  64 MB (tf32)
__device__ float g_v[(long long)MTOK * HKD];          //  64 MB (tf32)
__device__ float g_sc[(long long)BH * SS * SS];       // 512 MB scores / probs
__device__ float g_at[(long long)MTOK * HKD];         //  64 MB (tf32)
__device__ float g_ao[(long long)MTOK * DD];          //   8 MB (fp32)
__device__ float g_z [(long long)MTOK * DD];          //   8 MB (fp32 exact)
__device__ float g_ztf[(long long)MTOK * DD];         //   8 MB (tf32 copy)
__device__ float g_h [(long long)MTOK * FFD];         //  16 MB (tf32)
__device__ float g_f [(long long)MTOK * DD];          //   8 MB (fp32)
// pre-converted inputs
__device__ float g_x [(long long)MTOK * DD];          //   8 MB (tf32)
__device__ float g_wq[(long long)DD * HKD];           //   2 MB
__device__ float g_wk[(long long)DD * HKD];
__device__ float g_wv[(long long)DD * HKD];
__device__ float g_wo[(long long)HKD * DD];
__device__ float g_w1[(long long)DD * FFD];
__device__ float g_w2[(long long)FFD * DD];

// ---------------------------------------------------------------------------
// tf32 helpers
// ---------------------------------------------------------------------------
__device__ __forceinline__ unsigned f2tf(float f) {
    unsigned u;
    asm("cvt.rna.tf32.f32 %0, %1;" : "=r"(u) : "f"(f));
    return u;
}
__device__ __forceinline__ float f2tf_f(float f) {
    return __uint_as_float(f2tf(f));
}

__device__ __forceinline__ void mma_tf32(
    float& c0, float& c1, float& c2, float& c3,
    unsigned a0, unsigned a1, unsigned a2, unsigned a3,
    unsigned b0, unsigned b1)
{
    asm volatile(
        "mma.sync.aligned.m16n8k8.row.col.f32.tf32.tf32.f32 "
        "{%0,%1,%2,%3}, {%4,%5,%6,%7}, {%8,%9}, {%0,%1,%2,%3};"
        : "+f"(c0), "+f"(c1), "+f"(c2), "+f"(c3)
        : "r"(a0), "r"(a1), "r"(a2), "r"(a3), "r"(b0), "r"(b1));
}

#define CP_ASYNC16(saddr, gptr) \
    asm volatile("cp.async.cg.shared.global [%0], [%1], 16;" \
                 :: "r"(saddr), "l"(gptr))
#define CP_COMMIT()  asm volatile("cp.async.commit_group;" ::: "memory")
#define CP_WAIT_1()  asm volatile("cp.async.wait_group 1;" ::: "memory")
#define CP_WAIT_0()  asm volatile("cp.async.wait_group 0;" ::: "memory")

// ---------------------------------------------------------------------------
// Elementwise fp32 -> tf32-bits conversion (for inputs)
// ---------------------------------------------------------------------------
__global__ void __launch_bounds__(256)
conv_tf32(const float* __restrict__ src, float* __restrict__ dst, int n)
{
    int i = blockIdx.x * 256 + threadIdx.x;
    if (i < n) dst[i] = f2tf_f(src[i]);
}

// ---------------------------------------------------------------------------
// Batched tf32 tensor-core GEMM, 2-stage cp.async double-buffered.
// C = alpha * (A @ B(^T) + bias), optional relu, optional tf32-convert on store.
// Operands must already contain tf32 bit patterns.
// Block 128x128x32, 256 threads = 8 warps (2M x 4N), warp 64x32 m16n8k8.
// All dims are multiples of tile sizes for every call in this file.
// ---------------------------------------------------------------------------
#define BM 128
#define BN 128
#define BK 32

template <bool TRANS_B>
__global__ void __launch_bounds__(256)
mma_gemm(const float* __restrict__ A, const float* __restrict__ B,
         float* __restrict__ C, const float* __restrict__ bias,
         int K, int lda, int ldb, int ldc,
         int batch_div,
         long long sAo, long long sAi,
         long long sBo, long long sBi,
         long long sCo, long long sCi,
         float alpha, int relu, int convout)
{
    const int z  = blockIdx.z;
    const int zo = z / batch_div;
    const int zi = z - zo * batch_div;
    A += zo * sAo + zi * sAi;
    B += zo * sBo + zi * sBi;
    C += zo * sCo + zi * sCi;

    constexpr int BROWS = TRANS_B ? BN : BK;
    constexpr int BPAD  = TRANS_B ? 36 : 136;

    extern __shared__ unsigned smem[];
    // A: [2][BM][36]  (36%32=4 -> fragment banks g*4+tg, conflict-free)
    // B-NN: [2][32][136] (136%32=8 -> banks tg*8+g), B-TN: [2][128][36]
    unsigned (*As)[BM][36]       = (unsigned (*)[BM][36])smem;
    unsigned (*Bs)[BROWS][BPAD]  = (unsigned (*)[BROWS][BPAD])(smem + 2 * BM * 36);

    const int tid  = threadIdx.x;
    const int lane = tid & 31;
    const int wrp  = tid >> 5;
    const int m0   = blockIdx.y * BM;
    const int n0   = blockIdx.x * BN;

    const int wm = (wrp & 1) * 64;
    const int wn = (wrp >> 1) * 32;
    const int g  = lane >> 2;
    const int tg = lane & 3;

    // per-thread load coordinates (4 x 16B each for A and B)
    const int aRow = tid >> 3;            // 0..31 (+32*i)
    const int aCol = (tid & 7) * 4;
    const int bRowNN = tid >> 5;          // 0..7 (+8*i)
    const int bColNN = (tid & 31) * 4;

    float acc[4][4][4];
#pragma unroll
    for (int mi = 0; mi < 4; mi++)
#pragma unroll
        for (int ni = 0; ni < 4; ni++)
#pragma unroll
            for (int r = 0; r < 4; r++) acc[mi][ni][r] = 0.f;

    // ---- stage loader ----
    auto issue = [&](int st, int k0) {
#pragma unroll
        for (int i = 0; i < 4; i++) {
            const int row = aRow + i * 32;
            const float* gp = A + (long long)(m0 + row) * lda + k0 + aCol;
            unsigned sa = (unsigned)__cvta_generic_to_shared(&As[st][row][aCol]);
            CP_ASYNC16(sa, gp);
        }
        if (!TRANS_B) {
#pragma unroll
            for (int i = 0; i < 4; i++) {
                const int row = bRowNN + i * 8;
                const float* gp = B + (long long)(k0 + row) * ldb + n0 + bColNN;
                unsigned sa = (unsigned)__cvta_generic_to_shared(&Bs[st][row][bColNN]);
                CP_ASYNC16(sa, gp);
            }
        } else {
#pragma unroll
            for (int i = 0; i < 4; i++) {
                const int row = aRow + i * 32;
                const float* gp = B + (long long)(n0 + row) * ldb + k0 + aCol;
                unsigned sa = (unsigned)__cvta_generic_to_shared(&Bs[st][row][aCol]);
                CP_ASYNC16(sa, gp);
            }
        }
        CP_COMMIT();
    };

    const int T = K / BK;
    issue(0, 0);

    for (int it = 0; it < T; it++) {
        const int st = it & 1;
        if (it + 1 < T) {
            issue(st ^ 1, (it + 1) * BK);
            CP_WAIT_1();
        } else {
            CP_WAIT_0();
        }
        __syncthreads();

#pragma unroll
        for (int ks = 0; ks < BK; ks += 8) {
            unsigned a[4][4];
#pragma unroll
            for (int mi = 0; mi < 4; mi++) {
                const int r = wm + mi * 16 + g;
                a[mi][0] = As[st][r    ][ks + tg];
                a[mi][1] = As[st][r + 8][ks + tg];
                a[mi][2] = As[st][r    ][ks + tg + 4];
                a[mi][3] = As[st][r + 8][ks + tg + 4];
            }
            unsigned b[4][2];
#pragma unroll
            for (int ni = 0; ni < 4; ni++) {
                const int n = wn + ni * 8 + g;
                if (!TRANS_B) {
                    b[ni][0] = Bs[st][ks + tg    ][n];
                    b[ni][1] = Bs[st][ks + tg + 4][n];
                } else {
                    b[ni][0] = Bs[st][n][ks + tg];
                    b[ni][1] = Bs[st][n][ks + tg + 4];
                }
            }
#pragma unroll
            for (int mi = 0; mi < 4; mi++)
#pragma unroll
                for (int ni = 0; ni < 4; ni++)
                    mma_tf32(acc[mi][ni][0], acc[mi][ni][1],
                             acc[mi][ni][2], acc[mi][ni][3],
                             a[mi][0], a[mi][1], a[mi][2], a[mi][3],
                             b[ni][0], b[ni][1]);
        }
        __syncthreads();
    }

    // ---- epilogue ----
#pragma unroll
    for (int mi = 0; mi < 4; mi++) {
        const int r0 = m0 + wm + mi * 16 + g;
#pragma unroll
        for (int ni = 0; ni < 4; ni++) {
            const int col = n0 + wn + ni * 8 + tg * 2;
            float v0 = acc[mi][ni][0], v1 = acc[mi][ni][1];
            float v2 = acc[mi][ni][2], v3 = acc[mi][ni][3];
            if (bias) {
                const float b0 = bias[col], b1 = bias[col + 1];
                v0 += b0; v1 += b1; v2 += b0; v3 += b1;
            }
            v0 *= alpha; v1 *= alpha; v2 *= alpha; v3 *= alpha;
            if (relu) {
                v0 = fmaxf(v0, 0.f); v1 = fmaxf(v1, 0.f);
                v2 = fmaxf(v2, 0.f); v3 = fmaxf(v3, 0.f);
            }
            if (convout) {
                v0 = f2tf_f(v0); v1 = f2tf_f(v1);
                v2 = f2tf_f(v2); v3 = f2tf_f(v3);
            }
            *(float2*)(C + (long long)r0 * ldc + col)       = make_float2(v0, v1);
            *(float2*)(C + (long long)(r0 + 8) * ldc + col) = make_float2(v2, v3);
        }
    }
}

// ---------------------------------------------------------------------------
// Row softmax over rows of length 2048; writes tf32-converted probs
// (identical numerics to converting at the PV GEMM load).
// ---------------------------------------------------------------------------
__global__ void __launch_bounds__(256)
softmax_kernel(float* __restrict__ s)
{
    float* row = s + (long long)blockIdx.x * SS;
    const int t = threadIdx.x;
    float v[8];
#pragma unroll
    for (int i = 0; i < 8; i++) v[i] = row[t + i * 256];

    float m = v[0];
#pragma unroll
    for (int i = 1; i < 8; i++) m = fmaxf(m, v[i]);

    __shared__ float sh[256];
    sh[t] = m; __syncthreads();
    for (int st = 128; st; st >>= 1) {
        if (t < st) sh[t] = fmaxf(sh[t], sh[t + st]);
        __syncthreads();
    }
    m = sh[0]; __syncthreads();

    float sum = 0.f;
#pragma unroll
    for (int i = 0; i < 8; i++) { v[i] = expf(v[i] - m); sum += v[i]; }

    sh[t] = sum; __syncthreads();
    for (int st = 128; st; st >>= 1) {
        if (t < st) sh[t] += sh[t + st];
        __syncthreads();
    }
    const float inv = 1.f / sh[0];
#pragma unroll
    for (int i = 0; i < 8; i++) row[t + i * 256] = f2tf_f(v[i] * inv);
}

// ---------------------------------------------------------------------------
// LayerNorm (+ residual). D = 256 = blockDim.
//   add_before = 0 :  out = LN(a)*g + b + r  ; out_tf gets tf32 copy
//   add_before = 1 :  out = LN(a + r)*g + b
// ---------------------------------------------------------------------------
__global__ void __launch_bounds__(256)
ln_kernel(const float* __restrict__ a, const float* __restrict__ r,
          const float* __restrict__ g, const float* __restrict__ b,
          float* __restrict__ out, float* __restrict__ out_tf, int add_before)
{
    const int t = threadIdx.x;
    const long long base = (long long)blockIdx.x * DD;
    const float av = a[base + t];
    const float rv = r[base + t];
    const float val = add_before ? (av + rv) : av;

    __shared__ float sh[256];
    sh[t] = val; __syncthreads();
    for (int st = 128; st; st >>= 1) {
        if (t < st) sh[t] += sh[t + st];
        __syncthreads();
    }
    const float mean = sh[0] * (1.f / 256.f);
    __syncthreads();

    const float d = val - mean;
    sh[t] = d * d; __syncthreads();
    for (int st = 128; st; st >>= 1) {
        if (t < st) sh[t] += sh[t + st];
        __syncthreads();
    }
    const float var = sh[0] * (1.f / 256.f);

    const float y = d * rsqrtf(var + 1e-3f) * g[t] + b[t];
    const float o = add_before ? y : (y + rv);
    out[base + t] = o;
    if (out_tf) out_tf[base + t] = f2tf_f(o);
}

// ---------------------------------------------------------------------------
// Launch
// ---------------------------------------------------------------------------
extern "C" void kernel_launch(void* const* d_in, const int* in_sizes, int n_in,
                              void* d_out, int out_size)
{
    const float* x   = (const float*)d_in[0];
    const float* Wq  = (const float*)d_in[1];
    const float* bq  = (const float*)d_in[2];
    const float* Wk  = (const float*)d_in[3];
    const float* bk  = (const float*)d_in[4];
    const float* Wv  = (const float*)d_in[5];
    const float* bv  = (const float*)d_in[6];
    const float* Wo  = (const float*)d_in[7];
    const float* bo  = (const float*)d_in[8];
    const float* g1  = (const float*)d_in[9];
    const float* be1 = (const float*)d_in[10];
    const float* W1  = (const float*)d_in[11];
    const float* bb1 = (const float*)d_in[12];
    const float* W2  = (const float*)d_in[13];
    const float* bb2 = (const float*)d_in[14];
    const float* g2  = (const float*)d_in[15];
    const float* be2 = (const float*)d_in[16];
    float* out = (float*)d_out;

    float *q, *k, *v, *sc, *at, *ao, *zz, *ztf, *hh, *ff;
    float *xc, *wq, *wk, *wv, *wo, *w1, *w2;
    cudaGetSymbolAddress((void**)&q,  g_q);
    cudaGetSymbolAddress((void**)&k,  g_k);
    cudaGetSymbolAddress((void**)&v,  g_v);
    cudaGetSymbolAddress((void**)&sc, g_sc);
    cudaGetSymbolAddress((void**)&at, g_at);
    cudaGetSymbolAddress((void**)&ao, g_ao);
    cudaGetSymbolAddress((void**)&zz, g_z);
    cudaGetSymbolAddress((void**)&ztf, g_ztf);
    cudaGetSymbolAddress((void**)&hh, g_h);
    cudaGetSymbolAddress((void**)&ff, g_f);
    cudaGetSymbolAddress((void**)&xc, g_x);
    cudaGetSymbolAddress((void**)&wq, g_wq);
    cudaGetSymbolAddress((void**)&wk, g_wk);
    cudaGetSymbolAddress((void**)&wv, g_wv);
    cudaGetSymbolAddress((void**)&wo, g_wo);
    cudaGetSymbolAddress((void**)&w1, g_w1);
    cudaGetSymbolAddress((void**)&w2, g_w2);

    // dynamic smem sizes
    const int smem_nn = (2 * BM * 36 + 2 * BK * 136) * 4;   // 71680
    const int smem_tn = (2 * BM * 36 + 2 * BN * 36) * 4;    // 73728
    cudaFuncSetAttribute(mma_gemm<false>,
                         cudaFuncAttributeMaxDynamicSharedMemorySize, smem_nn);
    cudaFuncSetAttribute(mma_gemm<true>,
                         cudaFuncAttributeMaxDynamicSharedMemorySize, smem_tn);

    const dim3 blk(256);
    const float qscale = 1.0f / 16.0f;   // 1/sqrt(KD)

    // ---- pre-convert inputs to tf32 bit patterns ---------------------------
    conv_tf32<<<(MTOK * DD) / 256, blk>>>(x,  xc, MTOK * DD);
    conv_tf32<<<(DD * HKD) / 256, blk>>>(Wq, wq, DD * HKD);
    conv_tf32<<<(DD * HKD) / 256, blk>>>(Wk, wk, DD * HKD);
    conv_tf32<<<(DD * HKD) / 256, blk>>>(Wv, wv, DD * HKD);
    conv_tf32<<<(HKD * DD) / 256, blk>>>(Wo, wo, HKD * DD);
    conv_tf32<<<(DD * FFD) / 256, blk>>>(W1, w1, DD * FFD);
    conv_tf32<<<(FFD * DD) / 256, blk>>>(W2, w2, FFD * DD);

    // ---- Q/K/V projections: [8192,256] x [256,2048] -> [b,s,h,e] (tf32 out)
    {
        dim3 grid(HKD / BN, MTOK / BM, 1);
        mma_gemm<false><<<grid, blk, smem_nn>>>(xc, wq, q, bq, DD, DD, HKD, HKD,
                                                1, 0, 0, 0, 0, 0, 0, qscale, 0, 1);
        mma_gemm<false><<<grid, blk, smem_nn>>>(xc, wk, k, bk, DD, DD, HKD, HKD,
                                                1, 0, 0, 0, 0, 0, 0, 1.f, 0, 1);
        mma_gemm<false><<<grid, blk, smem_nn>>>(xc, wv, v, bv, DD, DD, HKD, HKD,
                                                1, 0, 0, 0, 0, 0, 0, 1.f, 0, 1);
    }

    // ---- scores = Q K^T per (b,h): 32 x [2048,2048,256] (fp32 out) ----------
    {
        dim3 grid(SS / BN, SS / BM, BH);
        mma_gemm<true><<<grid, blk, smem_tn>>>(q, k, sc, nullptr, KDD,
                                               HKD, HKD, SS,
                                               HH,
                                               (long long)SS * HKD, (long long)KDD,
                                               (long long)SS * HKD, (long long)KDD,
                                               (long long)HH * SS * SS, (long long)SS * SS,
                                               1.f, 0, 0);
    }

    // ---- softmax (writes tf32 probs) ---------------------------------------
    softmax_kernel<<<BH * SS, blk>>>(sc);

    // ---- attn = P V per (b,h): 32 x [2048,256,2048] -> [b,s,h,e] (tf32 out) -
    {
        dim3 grid(KDD / BN, SS / BM, BH);
        mma_gemm<false><<<grid, blk, smem_nn>>>(sc, v, at, nullptr, SS,
                                                SS, HKD, HKD,
                                                HH,
                                                (long long)HH * SS * SS, (long long)SS * SS,
                                                (long long)SS * HKD, (long long)KDD,
                                                (long long)SS * HKD, (long long)KDD,
                                                1.f, 0, 1);
    }

    // ---- output projection: [8192,2048] x [2048,256] (fp32 out) -------------
    {
        dim3 grid(DD / BN, MTOK / BM, 1);
        mma_gemm<false><<<grid, blk, smem_nn>>>(at, wo, ao, bo, HKD, HKD, DD, DD,
                                                1, 0, 0, 0, 0, 0, 0, 1.f, 0, 0);
    }

    // ---- z = LN(attn_out) + x  (exact + tf32 copy) --------------------------
    ln_kernel<<<MTOK, blk>>>(ao, x, g1, be1, zz, ztf, 0);

    // ---- FFN ----------------------------------------------------------------
    {
        dim3 grid(FFD / BN, MTOK / BM, 1);
        mma_gemm<false><<<grid, blk, smem_nn>>>(ztf, w1, hh, bb1, DD, DD, FFD, FFD,
                                                1, 0, 0, 0, 0, 0, 0, 1.f, 1, 1);
    }
    {
        dim3 grid(DD / BN, MTOK / BM, 1);
        mma_gemm<false><<<grid, blk, smem_nn>>>(hh, w2, ff, bb2, FFD, FFD, DD, DD,
                                                1, 0, 0, 0, 0, 0, 0, 1.f, 0, 0);
    }

    // ---- out = LN(f + z) ----------------------------------------------------
    ln_kernel<<<MTOK, blk>>>(ff, zz, g2, be2, out, nullptr, 1);
}

// round 7
// speedup vs baseline: 5.5069x; 1.6733x over previous
#include <cuda_runtime.h>
#include <cuda_fp16.h>
#include <math.h>
#include <stdint.h>

// ---------------------------------------------------------------------------
// Problem constants
// ---------------------------------------------------------------------------
#define MB   4
#define SS   2048
#define DD   256
#define HH   8
#define KDD  256
#define FFD  512
#define MTOK (MB * SS)        // 8192
#define HKD  (HH * KDD)       // 2048
#define BH   (MB * HH)        // 32

// ---------------------------------------------------------------------------
// Static scratch (device .bss — no runtime allocation)
// GEMM operands are fp16 (K-contiguous, TN layout); accumulators/outputs fp32
// unless consumed by another GEMM.
// ---------------------------------------------------------------------------
__device__ __align__(256) __half g_q16 [(long long)MTOK * HKD];     // [b,s,h,e]
__device__ __align__(256) __half g_k16 [(long long)MTOK * HKD];
__device__ __align__(256) __half g_v16 [(long long)MTOK * HKD];
__device__ __align__(256) __half g_vt16[(long long)BH * KDD * SS];  // [bh,e,s]
__device__ float g_sc[(long long)BH * SS * SS];                     // fp32 scores
__device__ __align__(256) __half g_p16 [(long long)BH * SS * SS];   // fp16 probs
__device__ __align__(256) __half g_at16[(long long)MTOK * HKD];     // [b,s,h,e]
__device__ float g_ao[(long long)MTOK * DD];
__device__ float g_z [(long long)MTOK * DD];
__device__ __align__(256) __half g_z16 [(long long)MTOK * DD];
__device__ __align__(256) __half g_h16 [(long long)MTOK * FFD];
__device__ float g_f [(long long)MTOK * DD];
// pre-converted / pre-transposed inputs (all [N,K] fp16)
__device__ __align__(256) __half g_x16 [(long long)MTOK * DD];
__device__ __align__(256) __half g_wq16[(long long)HKD * DD];
__device__ __align__(256) __half g_wk16[(long long)HKD * DD];
__device__ __align__(256) __half g_wv16[(long long)HKD * DD];
__device__ __align__(256) __half g_wo16[(long long)DD * HKD];
__device__ __align__(256) __half g_w116[(long long)FFD * DD];
__device__ __align__(256) __half g_w216[(long long)DD * FFD];

// ---------------------------------------------------------------------------
// PTX helpers
// ---------------------------------------------------------------------------
#define CP_ASYNC16(saddr, gptr) \
    asm volatile("cp.async.cg.shared.global [%0], [%1], 16;" :: "r"(saddr), "l"(gptr))
#define CP_COMMIT()  asm volatile("cp.async.commit_group;" ::: "memory")
#define CP_WAIT_1()  asm volatile("cp.async.wait_group 1;" ::: "memory")
#define CP_WAIT_0()  asm volatile("cp.async.wait_group 0;" ::: "memory")

__device__ __forceinline__ uint32_t smem_u32(const void* p) {
    uint32_t a;
    asm("{ .reg .u64 t; cvta.to.shared.u64 t, %1; cvt.u32.u64 %0, t; }" : "=r"(a) : "l"(p));
    return a;
}

// fp16 MMA: D(f32) += A(f16,row) x B(f16,col), 16x8x16
__device__ __forceinline__ void mma_f16(
    float& c0, float& c1, float& c2, float& c3,
    uint32_t a0, uint32_t a1, uint32_t a2, uint32_t a3,
    uint32_t b0, uint32_t b1)
{
    asm volatile(
        "mma.sync.aligned.m16n8k16.row.col.f32.f16.f16.f32 "
        "{%0,%1,%2,%3}, {%4,%5,%6,%7}, {%8,%9}, {%0,%1,%2,%3};"
        : "+f"(c0), "+f"(c1), "+f"(c2), "+f"(c3)
        : "r"(a0), "r"(a1), "r"(a2), "r"(a3), "r"(b0), "r"(b1));
}

// ---------------------------------------------------------------------------
// TN fp16 tensor-core GEMM: C[M,N] = alpha*(A[M,K] @ B[N,K]^T + bias),
// optional relu; output fp32 or fp16 (outhalf).
// Block 128x128, K-chunk 64 halves, 2-stage cp.async, 256 thr = 8 warps
// (2M x 4N), warp 64x32 via m16n8k16. All dims multiples of tile sizes.
// smem per operand tile: 128 rows x 36 words (32 data + 4 pad; pad%32=4 ->
// fragment banks (4g+tg)%32, conflict-free).
// ---------------------------------------------------------------------------
#define BKH 64
#define ROWW 36
#define OPW  (128 * ROWW)           // words per operand tile (4608)
#define STW  (2 * OPW)              // words per stage (9216)
#define HG_SMEM (2 * STW * 4)       // 73728 bytes

__global__ void __launch_bounds__(256)
hgemm(const __half* __restrict__ A, const __half* __restrict__ B,
      void* __restrict__ Cv, const float* __restrict__ bias,
      int K, int lda, int ldb, int ldc,
      int batch_div,
      long long sAo, long long sAi,
      long long sBo, long long sBi,
      long long sCo, long long sCi,
      float alpha, int relu, int outhalf)
{
    extern __shared__ uint32_t smw[];
    const uint32_t sbase = smem_u32(smw);

    const int z  = blockIdx.z;
    const int zo = z / batch_div;
    const int zi = z - zo * batch_div;
    A += zo * sAo + zi * sAi;
    B += zo * sBo + zi * sBi;

    const int tid  = threadIdx.x;
    const int lane = tid & 31;
    const int wrp  = tid >> 5;
    const int m0   = blockIdx.y * 128;
    const int n0   = blockIdx.x * 128;

    const int wm = (wrp & 1) * 64;
    const int wn = (wrp >> 1) * 32;
    const int g  = lane >> 2;
    const int tg = lane & 3;

    const __half* Ab = A + (long long)m0 * lda;
    const __half* Bb = B + (long long)n0 * ldb;

    float acc[4][4][4];
#pragma unroll
    for (int mi = 0; mi < 4; mi++)
#pragma unroll
        for (int ni = 0; ni < 4; ni++)
#pragma unroll
            for (int r = 0; r < 4; r++) acc[mi][ni][r] = 0.f;

    // per-thread load coords: 1024 16B-chunks per operand, 4 per thread
    const int lrow = tid >> 3;          // 0..31 (+32*i)
    const int lk8  = tid & 7;           // 16B chunk within 128B row

    auto issue = [&](int st, int k0) {
        const uint32_t s0 = sbase + (st * STW) * 4;
#pragma unroll
        for (int i = 0; i < 4; i++) {
            const int row = lrow + i * 32;
            const uint32_t off = (row * ROWW + lk8 * 4) * 4;
            CP_ASYNC16(s0 + off,           Ab + (long long)row * lda + k0 + lk8 * 8);
            CP_ASYNC16(s0 + OPW * 4 + off, Bb + (long long)row * ldb + k0 + lk8 * 8);
        }
        CP_COMMIT();
    };

    const int T = K / BKH;
    issue(0, 0);

    for (int it = 0; it < T; it++) {
        const int st = it & 1;
        if (it + 1 < T) {
            issue(st ^ 1, (it + 1) * BKH);
            CP_WAIT_1();
        } else {
            CP_WAIT_0();
        }
        __syncthreads();

        const uint32_t* As = smw + st * STW;
        const uint32_t* Bs = As + OPW;

#pragma unroll
        for (int ks = 0; ks < 4; ks++) {            // 4 x K=16
            const int kw = ks * 8;
            uint32_t a[4][4];
#pragma unroll
            for (int mi = 0; mi < 4; mi++) {
                const int r = (wm + mi * 16 + g) * ROWW + kw + tg;
                a[mi][0] = As[r];
                a[mi][1] = As[r + 8 * ROWW];
                a[mi][2] = As[r + 4];
                a[mi][3] = As[r + 8 * ROWW + 4];
            }
            uint32_t b[4][2];
#pragma unroll
            for (int ni = 0; ni < 4; ni++) {
                const int r = (wn + ni * 8 + g) * ROWW + kw + tg;
                b[ni][0] = Bs[r];
                b[ni][1] = Bs[r + 4];
            }
#pragma unroll
            for (int mi = 0; mi < 4; mi++)
#pragma unroll
                for (int ni = 0; ni < 4; ni++)
                    mma_f16(acc[mi][ni][0], acc[mi][ni][1],
                            acc[mi][ni][2], acc[mi][ni][3],
                            a[mi][0], a[mi][1], a[mi][2], a[mi][3],
                            b[ni][0], b[ni][1]);
        }
        __syncthreads();
    }

    // ---- epilogue ----
    float*  Cf = (float*)Cv  + zo * sCo + zi * sCi;
    __half* Ch = (__half*)Cv + zo * sCo + zi * sCi;
#pragma unroll
    for (int mi = 0; mi < 4; mi++) {
        const int r0 = m0 + wm + mi * 16 + g;
#pragma unroll
        for (int ni = 0; ni < 4; ni++) {
            const int col = n0 + wn + ni * 8 + tg * 2;
            float v0 = acc[mi][ni][0], v1 = acc[mi][ni][1];
            float v2 = acc[mi][ni][2], v3 = acc[mi][ni][3];
            if (bias) {
                const float b0 = bias[col], b1 = bias[col + 1];
                v0 += b0; v1 += b1; v2 += b0; v3 += b1;
            }
            v0 *= alpha; v1 *= alpha; v2 *= alpha; v3 *= alpha;
            if (relu) {
                v0 = fmaxf(v0, 0.f); v1 = fmaxf(v1, 0.f);
                v2 = fmaxf(v2, 0.f); v3 = fmaxf(v3, 0.f);
            }
            if (outhalf) {
                *(__half2*)(Ch + (long long)r0 * ldc + col) =
                    __floats2half2_rn(v0, v1);
                *(__half2*)(Ch + (long long)(r0 + 8) * ldc + col) =
                    __floats2half2_rn(v2, v3);
            } else {
                *(float2*)(Cf + (long long)r0 * ldc + col)       = make_float2(v0, v1);
                *(float2*)(Cf + (long long)(r0 + 8) * ldc + col) = make_float2(v2, v3);
            }
        }
    }
}

// ---------------------------------------------------------------------------
// fp32 -> fp16 elementwise (x)
// ---------------------------------------------------------------------------
__global__ void __launch_bounds__(256)
conv_h(const float* __restrict__ src, __half* __restrict__ dst, int n)
{
    int i = blockIdx.x * 256 + threadIdx.x;
    if (i < n) dst[i] = __float2half_rn(src[i]);
}

// src [K,N] fp32 -> dst [N,K] fp16 (weights). Dims multiples of 32.
__global__ void __launch_bounds__(256)
convT_h(const float* __restrict__ src, __half* __restrict__ dst, int Kd, int Nd)
{
    __shared__ float t[32][33];
    const int tx = threadIdx.x & 31, ty = threadIdx.x >> 5;  // 32x8
    const int k0 = blockIdx.x * 32, n0 = blockIdx.y * 32;
#pragma unroll
    for (int i = ty; i < 32; i += 8)
        t[i][tx] = src[(long long)(k0 + i) * Nd + n0 + tx];
    __syncthreads();
#pragma unroll
    for (int i = ty; i < 32; i += 8)
        dst[(long long)(n0 + i) * Kd + k0 + tx] = __float2half_rn(t[tx][i]);
}

// v[b,s,h,e] fp16 -> vt[bh,e,s] fp16
__global__ void __launch_bounds__(256)
vtrans_h(const __half* __restrict__ v, __half* __restrict__ vt)
{
    __shared__ __half t[32][33];
    const int tx = threadIdx.x & 31, ty = threadIdx.x >> 5;
    const int bh = blockIdx.z, b = bh >> 3, h = bh & 7;
    const int s0 = blockIdx.x * 32, e0 = blockIdx.y * 32;
#pragma unroll
    for (int i = ty; i < 32; i += 8)
        t[i][tx] = v[((long long)(b * SS + s0 + i) * HH + h) * KDD + e0 + tx];
    __syncthreads();
#pragma unroll
    for (int i = ty; i < 32; i += 8)
        vt[((long long)bh * KDD + e0 + i) * SS + s0 + tx] = t[tx][i];
}

// ---------------------------------------------------------------------------
// Row softmax over rows of length 2048 (fp32 in, fp16 probs out)
// ---------------------------------------------------------------------------
__global__ void __launch_bounds__(256)
softmax_kernel(const float* __restrict__ s, __half* __restrict__ p)
{
    const float* row  = s + (long long)blockIdx.x * SS;
    __half*      rowp = p + (long long)blockIdx.x * SS;
    const int t = threadIdx.x;
    float v[8];
#pragma unroll
    for (int i = 0; i < 8; i++) v[i] = row[t + i * 256];

    float m = v[0];
#pragma unroll
    for (int i = 1; i < 8; i++) m = fmaxf(m, v[i]);

    __shared__ float sh[256];
    sh[t] = m; __syncthreads();
    for (int st = 128; st; st >>= 1) {
        if (t < st) sh[t] = fmaxf(sh[t], sh[t + st]);
        __syncthreads();
    }
    m = sh[0]; __syncthreads();

    float sum = 0.f;
#pragma unroll
    for (int i = 0; i < 8; i++) { v[i] = expf(v[i] - m); sum += v[i]; }

    sh[t] = sum; __syncthreads();
    for (int st = 128; st; st >>= 1) {
        if (t < st) sh[t] += sh[t + st];
        __syncthreads();
    }
    const float inv = 1.f / sh[0];
#pragma unroll
    for (int i = 0; i < 8; i++) rowp[t + i * 256] = __float2half_rn(v[i] * inv);
}

// ---------------------------------------------------------------------------
// LayerNorm (+ residual). D = 256 = blockDim.
//   add_before = 0 :  out = LN(a)*g + b + r ; out16 gets fp16 copy
//   add_before = 1 :  out = LN(a + r)*g + b
// ---------------------------------------------------------------------------
__global__ void __launch_bounds__(256)
ln_kernel(const float* __restrict__ a, const float* __restrict__ r,
          const float* __restrict__ g, const float* __restrict__ b,
          float* __restrict__ out, __half* __restrict__ out16, int add_before)
{
    const int t = threadIdx.x;
    const long long base = (long long)blockIdx.x * DD;
    const float av = a[base + t];
    const float rv = r[base + t];
    const float val = add_before ? (av + rv) : av;

    __shared__ float sh[256];
    sh[t] = val; __syncthreads();
    for (int st = 128; st; st >>= 1) {
        if (t < st) sh[t] += sh[t + st];
        __syncthreads();
    }
    const float mean = sh[0] * (1.f / 256.f);
    __syncthreads();

    const float d = val - mean;
    sh[t] = d * d; __syncthreads();
    for (int st = 128; st; st >>= 1) {
        if (t < st) sh[t] += sh[t + st];
        __syncthreads();
    }
    const float var = sh[0] * (1.f / 256.f);

    const float y = d * rsqrtf(var + 1e-3f) * g[t] + b[t];
    const float o = add_before ? y : (y + rv);
    out[base + t] = o;
    if (out16) out16[base + t] = __float2half_rn(o);
}

// ---------------------------------------------------------------------------
// Launch
// ---------------------------------------------------------------------------
extern "C" void kernel_launch(void* const* d_in, const int* in_sizes, int n_in,
                              void* d_out, int out_size)
{
    const float* x   = (const float*)d_in[0];
    const float* Wq  = (const float*)d_in[1];
    const float* bq  = (const float*)d_in[2];
    const float* Wk  = (const float*)d_in[3];
    const float* bk  = (const float*)d_in[4];
    const float* Wv  = (const float*)d_in[5];
    const float* bv  = (const float*)d_in[6];
    const float* Wo  = (const float*)d_in[7];
    const float* bo  = (const float*)d_in[8];
    const float* g1  = (const float*)d_in[9];
    const float* be1 = (const float*)d_in[10];
    const float* W1  = (const float*)d_in[11];
    const float* bb1 = (const float*)d_in[12];
    const float* W2  = (const float*)d_in[13];
    const float* bb2 = (const float*)d_in[14];
    const float* g2  = (const float*)d_in[15];
    const float* be2 = (const float*)d_in[16];
    float* out = (float*)d_out;

    __half *q16, *k16, *v16, *vt16, *p16, *at16, *z16, *h16;
    __half *x16, *wq16, *wk16, *wv16, *wo16, *w116, *w216;
    float *sc, *ao, *zz, *ff;
    cudaGetSymbolAddress((void**)&q16,  g_q16);
    cudaGetSymbolAddress((void**)&k16,  g_k16);
    cudaGetSymbolAddress((void**)&v16,  g_v16);
    cudaGetSymbolAddress((void**)&vt16, g_vt16);
    cudaGetSymbolAddress((void**)&p16,  g_p16);
    cudaGetSymbolAddress((void**)&at16, g_at16);
    cudaGetSymbolAddress((void**)&z16,  g_z16);
    cudaGetSymbolAddress((void**)&h16,  g_h16);
    cudaGetSymbolAddress((void**)&x16,  g_x16);
    cudaGetSymbolAddress((void**)&wq16, g_wq16);
    cudaGetSymbolAddress((void**)&wk16, g_wk16);
    cudaGetSymbolAddress((void**)&wv16, g_wv16);
    cudaGetSymbolAddress((void**)&wo16, g_wo16);
    cudaGetSymbolAddress((void**)&w116, g_w116);
    cudaGetSymbolAddress((void**)&w216, g_w216);
    cudaGetSymbolAddress((void**)&sc,   g_sc);
    cudaGetSymbolAddress((void**)&ao,   g_ao);
    cudaGetSymbolAddress((void**)&zz,   g_z);
    cudaGetSymbolAddress((void**)&ff,   g_f);

    cudaFuncSetAttribute(hgemm, cudaFuncAttributeMaxDynamicSharedMemorySize, HG_SMEM);

    const dim3 blk(256);
    const float qscale = 1.0f / 16.0f;   // 1/sqrt(KD)

    // ---- prep: x -> fp16; weights -> [N,K] fp16 -----------------------------
    conv_h<<<(MTOK * DD) / 256, blk>>>(x, x16, MTOK * DD);
    convT_h<<<dim3(DD / 32, HKD / 32), blk>>>(Wq, wq16, DD, HKD);
    convT_h<<<dim3(DD / 32, HKD / 32), blk>>>(Wk, wk16, DD, HKD);
    convT_h<<<dim3(DD / 32, HKD / 32), blk>>>(Wv, wv16, DD, HKD);
    convT_h<<<dim3(HKD / 32, DD / 32), blk>>>(Wo, wo16, HKD, DD);
    convT_h<<<dim3(DD / 32, FFD / 32), blk>>>(W1, w116, DD, FFD);
    convT_h<<<dim3(FFD / 32, DD / 32), blk>>>(W2, w216, FFD, DD);

    // ---- Q/K/V projections (TN) -> [b,s,h,e] fp16 ---------------------------
    {
        dim3 grid(HKD / 128, MTOK / 128, 1);
        hgemm<<<grid, blk, HG_SMEM>>>(x16, wq16, q16, bq, DD, DD, DD, HKD,
                                      1, 0, 0, 0, 0, 0, 0, qscale, 0, 1);
        hgemm<<<grid, blk, HG_SMEM>>>(x16, wk16, k16, bk, DD, DD, DD, HKD,
                                      1, 0, 0, 0, 0, 0, 0, 1.f, 0, 1);
        hgemm<<<grid, blk, HG_SMEM>>>(x16, wv16, v16, bv, DD, DD, DD, HKD,
                                      1, 0, 0, 0, 0, 0, 0, 1.f, 0, 1);
    }

    // ---- vt[bh,e,s] ---------------------------------------------------------
    vtrans_h<<<dim3(SS / 32, KDD / 32, BH), blk>>>(v16, vt16);

    // ---- scores = Q K^T per (b,h) (fp32 out) --------------------------------
    {
        dim3 grid(SS / 128, SS / 128, BH);
        hgemm<<<grid, blk, HG_SMEM>>>(q16, k16, sc, nullptr, KDD,
                                      HKD, HKD, SS,
                                      HH,
                                      (long long)SS * HKD, (long long)KDD,
                                      (long long)SS * HKD, (long long)KDD,
                                      (long long)HH * SS * SS, (long long)SS * SS,
                                      1.f, 0, 0);
    }

    // ---- softmax (fp16 probs) ----------------------------------------------
    softmax_kernel<<<BH * SS, blk>>>(sc, p16);

    // ---- attn = P V  (TN: probs[S,S] @ vt[KD,S]^T) -> [b,s,h,e] fp16 --------
    {
        dim3 grid(KDD / 128, SS / 128, BH);
        hgemm<<<grid, blk, HG_SMEM>>>(p16, vt16, at16, nullptr, SS,
                                      SS, SS, HKD,
                                      HH,
                                      (long long)HH * SS * SS, (long long)SS * SS,
                                      (long long)HH * KDD * SS, (long long)KDD * SS,
                                      (long long)SS * HKD, (long long)KDD,
                                      1.f, 0, 1);
    }

    // ---- output projection (TN) fp32 out ------------------------------------
    {
        dim3 grid(DD / 128, MTOK / 128, 1);
        hgemm<<<grid, blk, HG_SMEM>>>(at16, wo16, ao, bo, HKD, HKD, HKD, DD,
                                      1, 0, 0, 0, 0, 0, 0, 1.f, 0, 0);
    }

    // ---- z = LN(attn_out) + x (fp32 exact + fp16 copy) ----------------------
    ln_kernel<<<MTOK, blk>>>(ao, x, g1, be1, zz, z16, 0);

    // ---- FFN ----------------------------------------------------------------
    {
        dim3 grid(FFD / 128, MTOK / 128, 1);
        hgemm<<<grid, blk, HG_SMEM>>>(z16, w116, h16, bb1, DD, DD, DD, FFD,
                                      1, 0, 0, 0, 0, 0, 0, 1.f, 1, 1);
    }
    {
        dim3 grid(DD / 128, MTOK / 128, 1);
        hgemm<<<grid, blk, HG_SMEM>>>(h16, w216, ff, bb2, FFD, FFD, FFD, DD,
                                      1, 0, 0, 0, 0, 0, 0, 1.f, 0, 0);
    }

    // ---- out = LN(f + z) ----------------------------------------------------
    ln_kernel<<<MTOK, blk>>>(ff, zz, g2, be2, out, nullptr, 1);
}

// round 10
// speedup vs baseline: 5.7442x; 1.0431x over previous
#include <cuda_runtime.h>
#include <cuda_fp16.h>
#include <math.h>
#include <stdint.h>

// ---------------------------------------------------------------------------
// Problem constants
// ---------------------------------------------------------------------------
#define MB   4
#define SS   2048
#define DD   256
#define HH   8
#define KDD  256
#define FFD  512
#define MTOK (MB * SS)        // 8192
#define HKD  (HH * KDD)       // 2048
#define BH   (MB * HH)        // 32

// ---------------------------------------------------------------------------
// Static scratch (device .bss — no runtime allocation)
// ---------------------------------------------------------------------------
__device__ __align__(256) __half g_q16 [(long long)MTOK * HKD];     // [b,s,h,e]
__device__ __align__(256) __half g_k16 [(long long)MTOK * HKD];
__device__ __align__(256) __half g_v16 [(long long)MTOK * HKD];
__device__ __align__(256) __half g_vt16[(long long)BH * KDD * SS];  // [bh,e,s]
__device__ float g_sc[(long long)BH * SS * SS];                     // fp32 scores
__device__ __align__(256) __half g_p16 [(long long)BH * SS * SS];   // fp16 probs
__device__ __align__(256) __half g_at16[(long long)MTOK * HKD];     // [b,s,h,e]
__device__ float g_ao[(long long)MTOK * DD];
__device__ float g_z [(long long)MTOK * DD];
__device__ __align__(256) __half g_z16 [(long long)MTOK * DD];
__device__ __align__(256) __half g_h16 [(long long)MTOK * FFD];
__device__ float g_f [(long long)MTOK * DD];
// pre-converted / pre-transposed inputs (all [N,K] fp16)
__device__ __align__(256) __half g_x16 [(long long)MTOK * DD];
__device__ __align__(256) __half g_wq16[(long long)HKD * DD];
__device__ __align__(256) __half g_wk16[(long long)HKD * DD];
__device__ __align__(256) __half g_wv16[(long long)HKD * DD];
__device__ __align__(256) __half g_wo16[(long long)DD * HKD];
__device__ __align__(256) __half g_w116[(long long)FFD * DD];
__device__ __align__(256) __half g_w216[(long long)DD * FFD];

// ---------------------------------------------------------------------------
// PTX helpers
// ---------------------------------------------------------------------------
#define CP_ASYNC16(saddr, gptr) \
    asm volatile("cp.async.cg.shared.global [%0], [%1], 16;" :: "r"(saddr), "l"(gptr))
#define CP_COMMIT()  asm volatile("cp.async.commit_group;" ::: "memory")
#define CP_WAIT_1()  asm volatile("cp.async.wait_group 1;" ::: "memory")
#define CP_WAIT_0()  asm volatile("cp.async.wait_group 0;" ::: "memory")

__device__ __forceinline__ uint32_t smem_u32(const void* p) {
    uint32_t a;
    asm("{ .reg .u64 t; cvta.to.shared.u64 t, %1; cvt.u32.u64 %0, t; }" : "=r"(a) : "l"(p));
    return a;
}

// fp16 MMA: D(f32) += A(f16,row) x B(f16,col), 16x8x16
__device__ __forceinline__ void mma_f16(
    float& c0, float& c1, float& c2, float& c3,
    uint32_t a0, uint32_t a1, uint32_t a2, uint32_t a3,
    uint32_t b0, uint32_t b1)
{
    asm volatile(
        "mma.sync.aligned.m16n8k16.row.col.f32.f16.f16.f32 "
        "{%0,%1,%2,%3}, {%4,%5,%6,%7}, {%8,%9}, {%0,%1,%2,%3};"
        : "+f"(c0), "+f"(c1), "+f"(c2), "+f"(c3)
        : "r"(a0), "r"(a1), "r"(a2), "r"(a3), "r"(b0), "r"(b1));
}

#define LDSM_X4(r0, r1, r2, r3, addr) \
    asm volatile("ldmatrix.sync.aligned.m8n8.x4.shared.b16 {%0,%1,%2,%3}, [%4];" \
                 : "=r"(r0), "=r"(r1), "=r"(r2), "=r"(r3) : "r"(addr))

// ---------------------------------------------------------------------------
// TN fp16 tensor-core GEMM: C[M,N] = alpha*(A[M,K] @ B[N,K]^T + bias),
// optional relu; output fp32 or fp16 (outhalf).
// Block 128x128, K-chunk 64 halves, 2-stage cp.async, 256 thr = 8 warps
// (2M x 4N), warp 64x32 via m16n8k16, fragments via ldmatrix.x4.
// smem per operand tile: 128 rows x 36 words (32 data + 4 pad); row stride
// 144B (=9*16B) -> ldmatrix lane addresses 16B-aligned and every 8-row
// phase hits 8 distinct 16B bank-groups.
// ---------------------------------------------------------------------------
#define BKH 64
#define ROWW 36
#define OPW  (128 * ROWW)           // words per operand tile (4608)
#define STW  (2 * OPW)              // words per stage (9216)
#define HG_SMEM (2 * STW * 4)       // 73728 bytes

__global__ void __launch_bounds__(256)
hgemm(const __half* __restrict__ A, const __half* __restrict__ B,
      void* __restrict__ Cv, const float* __restrict__ bias,
      int K, int lda, int ldb, int ldc,
      int batch_div,
      long long sAo, long long sAi,
      long long sBo, long long sBi,
      long long sCo, long long sCi,
      float alpha, int relu, int outhalf)
{
    extern __shared__ uint32_t smw[];
    const uint32_t sbase = smem_u32(smw);

    const int z  = blockIdx.z;
    const int zo = z / batch_div;
    const int zi = z - zo * batch_div;
    A += zo * sAo + zi * sAi;
    B += zo * sBo + zi * sBi;

    const int tid  = threadIdx.x;
    const int lane = tid & 31;
    const int wrp  = tid >> 5;
    const int m0   = blockIdx.y * 128;
    const int n0   = blockIdx.x * 128;

    const int wm = (wrp & 1) * 64;
    const int wn = (wrp >> 1) * 32;
    const int g  = lane >> 2;
    const int tg = lane & 3;

    const __half* Ab = A + (long long)m0 * lda;
    const __half* Bb = B + (long long)n0 * ldb;

    float acc[4][4][4];
#pragma unroll
    for (int mi = 0; mi < 4; mi++)
#pragma unroll
        for (int ni = 0; ni < 4; ni++)
#pragma unroll
            for (int r = 0; r < 4; r++) acc[mi][ni][r] = 0.f;

    // ---- ldmatrix lane-address bases (stage 0; add stage/k offsets later) --
    // A, m-tile mi: matrices {rows0-7@klo, rows8-15@klo, rows0-7@khi, rows8-15@khi}
    const int l15 = lane & 15;
    const int l7  = lane & 7;
    uint32_t aAddr[4], bAddr[2];
#pragma unroll
    for (int mi = 0; mi < 4; mi++)
        aAddr[mi] = sbase + ((wm + mi * 16 + l15) * ROWW + (lane >> 4) * 4) * 4;
    // B, n-tile pair p: matrices {nt(2p)@klo, nt(2p)@khi, nt(2p+1)@klo, nt(2p+1)@khi}
#pragma unroll
    for (int p = 0; p < 2; p++)
        bAddr[p] = sbase + OPW * 4 +
                   ((wn + p * 16 + (lane >> 4) * 8 + l7) * ROWW +
                    ((lane >> 3) & 1) * 4) * 4;

    // per-thread cp.async coords: 1024 16B-chunks per operand, 4 per thread
    const int lrow = tid >> 3;          // 0..31 (+32*i)
    const int lk8  = tid & 7;           // 16B chunk within 128B row

    auto issue = [&](int st, int k0) {
        const uint32_t s0 = sbase + (st * STW) * 4;
#pragma unroll
        for (int i = 0; i < 4; i++) {
            const int row = lrow + i * 32;
            const uint32_t off = (row * ROWW + lk8 * 4) * 4;
            CP_ASYNC16(s0 + off,           Ab + (long long)row * lda + k0 + lk8 * 8);
            CP_ASYNC16(s0 + OPW * 4 + off, Bb + (long long)row * ldb + k0 + lk8 * 8);
        }
        CP_COMMIT();
    };

    const int T = K / BKH;
    issue(0, 0);

    for (int it = 0; it < T; it++) {
        const int st = it & 1;
        if (it + 1 < T) {
            issue(st ^ 1, (it + 1) * BKH);
            CP_WAIT_1();
        } else {
            CP_WAIT_0();
        }
        __syncthreads();

        const uint32_t sOff = (uint32_t)(st * STW) * 4;

#pragma unroll
        for (int ks = 0; ks < 4; ks++) {            // 4 x K=16
            const uint32_t ko = sOff + ks * 32;     // 32B per k16 step
            uint32_t a[4][4];
#pragma unroll
            for (int mi = 0; mi < 4; mi++)
                LDSM_X4(a[mi][0], a[mi][1], a[mi][2], a[mi][3], aAddr[mi] + ko);
            uint32_t b[4][2];
#pragma unroll
            for (int p = 0; p < 2; p++)
                LDSM_X4(b[2 * p][0], b[2 * p][1], b[2 * p + 1][0], b[2 * p + 1][1],
                        bAddr[p] + ko);
#pragma unroll
            for (int mi = 0; mi < 4; mi++)
#pragma unroll
                for (int ni = 0; ni < 4; ni++)
                    mma_f16(acc[mi][ni][0], acc[mi][ni][1],
                            acc[mi][ni][2], acc[mi][ni][3],
                            a[mi][0], a[mi][1], a[mi][2], a[mi][3],
                            b[ni][0], b[ni][1]);
        }
        __syncthreads();
    }

    // ---- epilogue ----
    float*  Cf = (float*)Cv  + zo * sCo + zi * sCi;
    __half* Ch = (__half*)Cv + zo * sCo + zi * sCi;
#pragma unroll
    for (int mi = 0; mi < 4; mi++) {
        const int r0 = m0 + wm + mi * 16 + g;
#pragma unroll
        for (int ni = 0; ni < 4; ni++) {
            const int col = n0 + wn + ni * 8 + tg * 2;
            float v0 = acc[mi][ni][0], v1 = acc[mi][ni][1];
            float v2 = acc[mi][ni][2], v3 = acc[mi][ni][3];
            if (bias) {
                const float b0 = bias[col], b1 = bias[col + 1];
                v0 += b0; v1 += b1; v2 += b0; v3 += b1;
            }
            v0 *= alpha; v1 *= alpha; v2 *= alpha; v3 *= alpha;
            if (relu) {
                v0 = fmaxf(v0, 0.f); v1 = fmaxf(v1, 0.f);
                v2 = fmaxf(v2, 0.f); v3 = fmaxf(v3, 0.f);
            }
            if (outhalf) {
                *(__half2*)(Ch + (long long)r0 * ldc + col) =
                    __floats2half2_rn(v0, v1);
                *(__half2*)(Ch + (long long)(r0 + 8) * ldc + col) =
                    __floats2half2_rn(v2, v3);
            } else {
                *(float2*)(Cf + (long long)r0 * ldc + col)       = make_float2(v0, v1);
                *(float2*)(Cf + (long long)(r0 + 8) * ldc + col) = make_float2(v2, v3);
            }
        }
    }
}

// ---------------------------------------------------------------------------
// fp32 -> fp16 elementwise (x)
// ---------------------------------------------------------------------------
__global__ void __launch_bounds__(256)
conv_h(const float* __restrict__ src, __half* __restrict__ dst, int n)
{
    int i = blockIdx.x * 256 + threadIdx.x;
    if (i < n) dst[i] = __float2half_rn(src[i]);
}

// src [K,N] fp32 -> dst [N,K] fp16 (weights). Dims multiples of 32.
__global__ void __launch_bounds__(256)
convT_h(const float* __restrict__ src, __half* __restrict__ dst, int Kd, int Nd)
{
    __shared__ float t[32][33];
    const int tx = threadIdx.x & 31, ty = threadIdx.x >> 5;  // 32x8
    const int k0 = blockIdx.x * 32, n0 = blockIdx.y * 32;
#pragma unroll
    for (int i = ty; i < 32; i += 8)
        t[i][tx] = src[(long long)(k0 + i) * Nd + n0 + tx];
    __syncthreads();
#pragma unroll
    for (int i = ty; i < 32; i += 8)
        dst[(long long)(n0 + i) * Kd + k0 + tx] = __float2half_rn(t[tx][i]);
}

// v[b,s,h,e] fp16 -> vt[bh,e,s] fp16
__global__ void __launch_bounds__(256)
vtrans_h(const __half* __restrict__ v, __half* __restrict__ vt)
{
    __shared__ __half t[32][33];
    const int tx = threadIdx.x & 31, ty = threadIdx.x >> 5;
    const int bh = blockIdx.z, b = bh >> 3, h = bh & 7;
    const int s0 = blockIdx.x * 32, e0 = blockIdx.y * 32;
#pragma unroll
    for (int i = ty; i < 32; i += 8)
        t[i][tx] = v[((long long)(b * SS + s0 + i) * HH + h) * KDD + e0 + tx];
    __syncthreads();
#pragma unroll
    for (int i = ty; i < 32; i += 8)
        vt[((long long)bh * KDD + e0 + i) * SS + s0 + tx] = t[tx][i];
}

// ---------------------------------------------------------------------------
// Row softmax over rows of length 2048 (fp32 in, fp16 probs out)
// ---------------------------------------------------------------------------
__global__ void __launch_bounds__(256)
softmax_kernel(const float* __restrict__ s, __half* __restrict__ p)
{
    const float* row  = s + (long long)blockIdx.x * SS;
    __half*      rowp = p + (long long)blockIdx.x * SS;
    const int t = threadIdx.x;
    float v[8];
#pragma unroll
    for (int i = 0; i < 8; i++) v[i] = row[t + i * 256];

    float m = v[0];
#pragma unroll
    for (int i = 1; i < 8; i++) m = fmaxf(m, v[i]);

    __shared__ float sh[256];
    sh[t] = m; __syncthreads();
    for (int st = 128; st; st >>= 1) {
        if (t < st) sh[t] = fmaxf(sh[t], sh[t + st]);
        __syncthreads();
    }
    m = sh[0]; __syncthreads();

    float sum = 0.f;
#pragma unroll
    for (int i = 0; i < 8; i++) { v[i] = expf(v[i] - m); sum += v[i]; }

    sh[t] = sum; __syncthreads();
    for (int st = 128; st; st >>= 1) {
        if (t < st) sh[t] += sh[t + st];
        __syncthreads();
    }
    const float inv = 1.f / sh[0];
#pragma unroll
    for (int i = 0; i < 8; i++) rowp[t + i * 256] = __float2half_rn(v[i] * inv);
}

// ---------------------------------------------------------------------------
// LayerNorm (+ residual). D = 256 = blockDim.
//   add_before = 0 :  out = LN(a)*g + b + r ; out16 gets fp16 copy
//   add_before = 1 :  out = LN(a + r)*g + b
// ---------------------------------------------------------------------------
__global__ void __launch_bounds__(256)
ln_kernel(const float* __restrict__ a, const float* __restrict__ r,
          const float* __restrict__ g, const float* __restrict__ b,
          float* __restrict__ out, __half* __restrict__ out16, int add_before)
{
    const int t = threadIdx.x;
    const long long base = (long long)blockIdx.x * DD;
    const float av = a[base + t];
    const float rv = r[base + t];
    const float val = add_before ? (av + rv) : av;

    __shared__ float sh[256];
    sh[t] = val; __syncthreads();
    for (int st = 128; st; st >>= 1) {
        if (t < st) sh[t] += sh[t + st];
        __syncthreads();
    }
    const float mean = sh[0] * (1.f / 256.f);
    __syncthreads();

    const float d = val - mean;
    sh[t] = d * d; __syncthreads();
    for (int st = 128; st; st >>= 1) {
        if (t < st) sh[t] += sh[t + st];
        __syncthreads();
    }
    const float var = sh[0] * (1.f / 256.f);

    const float y = d * rsqrtf(var + 1e-3f) * g[t] + b[t];
    const float o = add_before ? y : (y + rv);
    out[base + t] = o;
    if (out16) out16[base + t] = __float2half_rn(o);
}

// ---------------------------------------------------------------------------
// Launch
// ---------------------------------------------------------------------------
extern "C" void kernel_launch(void* const* d_in, const int* in_sizes, int n_in,
                              void* d_out, int out_size)
{
    const float* x   = (const float*)d_in[0];
    const float* Wq  = (const float*)d_in[1];
    const float* bq  = (const float*)d_in[2];
    const float* Wk  = (const float*)d_in[3];
    const float* bk  = (const float*)d_in[4];
    const float* Wv  = (const float*)d_in[5];
    const float* bv  = (const float*)d_in[6];
    const float* Wo  = (const float*)d_in[7];
    const float* bo  = (const float*)d_in[8];
    const float* g1  = (const float*)d_in[9];
    const float* be1 = (const float*)d_in[10];
    const float* W1  = (const float*)d_in[11];
    const float* bb1 = (const float*)d_in[12];
    const float* W2  = (const float*)d_in[13];
    const float* bb2 = (const float*)d_in[14];
    const float* g2  = (const float*)d_in[15];
    const float* be2 = (const float*)d_in[16];
    float* out = (float*)d_out;

    __half *q16, *k16, *v16, *vt16, *p16, *at16, *z16, *h16;
    __half *x16, *wq16, *wk16, *wv16, *wo16, *w116, *w216;
    float *sc, *ao, *zz, *ff;
    cudaGetSymbolAddress((void**)&q16,  g_q16);
    cudaGetSymbolAddress((void**)&k16,  g_k16);
    cudaGetSymbolAddress((void**)&v16,  g_v16);
    cudaGetSymbolAddress((void**)&vt16, g_vt16);
    cudaGetSymbolAddress((void**)&p16,  g_p16);
    cudaGetSymbolAddress((void**)&at16, g_at16);
    cudaGetSymbolAddress((void**)&z16,  g_z16);
    cudaGetSymbolAddress((void**)&h16,  g_h16);
    cudaGetSymbolAddress((void**)&x16,  g_x16);
    cudaGetSymbolAddress((void**)&wq16, g_wq16);
    cudaGetSymbolAddress((void**)&wk16, g_wk16);
    cudaGetSymbolAddress((void**)&wv16, g_wv16);
    cudaGetSymbolAddress((void**)&wo16, g_wo16);
    cudaGetSymbolAddress((void**)&w116, g_w116);
    cudaGetSymbolAddress((void**)&w216, g_w216);
    cudaGetSymbolAddress((void**)&sc,   g_sc);
    cudaGetSymbolAddress((void**)&ao,   g_ao);
    cudaGetSymbolAddress((void**)&zz,   g_z);
    cudaGetSymbolAddress((void**)&ff,   g_f);

    cudaFuncSetAttribute(hgemm, cudaFuncAttributeMaxDynamicSharedMemorySize, HG_SMEM);

    const dim3 blk(256);
    const float qscale = 1.0f / 16.0f;   // 1/sqrt(KD)

    // ---- prep: x -> fp16; weights -> [N,K] fp16 -----------------------------
    conv_h<<<(MTOK * DD) / 256, blk>>>(x, x16, MTOK * DD);
    convT_h<<<dim3(DD / 32, HKD / 32), blk>>>(Wq, wq16, DD, HKD);
    convT_h<<<dim3(DD / 32, HKD / 32), blk>>>(Wk, wk16, DD, HKD);
    convT_h<<<dim3(DD / 32, HKD / 32), blk>>>(Wv, wv16, DD, HKD);
    convT_h<<<dim3(HKD / 32, DD / 32), blk>>>(Wo, wo16, HKD, DD);
    convT_h<<<dim3(DD / 32, FFD / 32), blk>>>(W1, w116, DD, FFD);
    convT_h<<<dim3(FFD / 32, DD / 32), blk>>>(W2, w216, FFD, DD);

    // ---- Q/K/V projections (TN) -> [b,s,h,e] fp16 ---------------------------
    {
        dim3 grid(HKD / 128, MTOK / 128, 1);
        hgemm<<<grid, blk, HG_SMEM>>>(x16, wq16, q16, bq, DD, DD, DD, HKD,
                                      1, 0, 0, 0, 0, 0, 0, qscale, 0, 1);
        hgemm<<<grid, blk, HG_SMEM>>>(x16, wk16, k16, bk, DD, DD, DD, HKD,
                                      1, 0, 0, 0, 0, 0, 0, 1.f, 0, 1);
        hgemm<<<grid, blk, HG_SMEM>>>(x16, wv16, v16, bv, DD, DD, DD, HKD,
                                      1, 0, 0, 0, 0, 0, 0, 1.f, 0, 1);
    }

    // ---- vt[bh,e,s] ---------------------------------------------------------
    vtrans_h<<<dim3(SS / 32, KDD / 32, BH), blk>>>(v16, vt16);

    // ---- scores = Q K^T per (b,h) (fp32 out) --------------------------------
    {
        dim3 grid(SS / 128, SS / 128, BH);
        hgemm<<<grid, blk, HG_SMEM>>>(q16, k16, sc, nullptr, KDD,
                                      HKD, HKD, SS,
                                      HH,
                                      (long long)SS * HKD, (long long)KDD,
                                      (long long)SS * HKD, (long long)KDD,
                                      (long long)HH * SS * SS, (long long)SS * SS,
                                      1.f, 0, 0);
    }

    // ---- softmax (fp16 probs) ----------------------------------------------
    softmax_kernel<<<BH * SS, blk>>>(sc, p16);

    // ---- attn = P V  (TN: probs[S,S] @ vt[KD,S]^T) -> [b,s,h,e] fp16 --------
    {
        dim3 grid(KDD / 128, SS / 128, BH);
        hgemm<<<grid, blk, HG_SMEM>>>(p16, vt16, at16, nullptr, SS,
                                      SS, SS, HKD,
                                      HH,
                                      (long long)HH * SS * SS, (long long)SS * SS,
                                      (long long)HH * KDD * SS, (long long)KDD * SS,
                                      (long long)SS * HKD, (long long)KDD,
                                      1.f, 0, 1);
    }

    // ---- output projection (TN) fp32 out ------------------------------------
    {
        dim3 grid(DD / 128, MTOK / 128, 1);
        hgemm<<<grid, blk, HG_SMEM>>>(at16, wo16, ao, bo, HKD, HKD, HKD, DD,
                                      1, 0, 0, 0, 0, 0, 0, 1.f, 0, 0);
    }

    // ---- z = LN(attn_out) + x (fp32 exact + fp16 copy) ----------------------
    ln_kernel<<<MTOK, blk>>>(ao, x, g1, be1, zz, z16, 0);

    // ---- FFN ----------------------------------------------------------------
    {
        dim3 grid(FFD / 128, MTOK / 128, 1);
        hgemm<<<grid, blk, HG_SMEM>>>(z16, w116, h16, bb1, DD, DD, DD, FFD,
                                      1, 0, 0, 0, 0, 0, 0, 1.f, 1, 1);
    }
    {
        dim3 grid(DD / 128, MTOK / 128, 1);
        hgemm<<<grid, blk, HG_SMEM>>>(h16, w216, ff, bb2, FFD, FFD, FFD, DD,
                                      1, 0, 0, 0, 0, 0, 0, 1.f, 0, 0);
    }

    // ---- out = LN(f + z) ----------------------------------------------------
    ln_kernel<<<MTOK, blk>>>(ff, zz, g2, be2, out, nullptr, 1);
}

// round 11
// speedup vs baseline: 7.0539x; 1.2280x over previous
#include <cuda_runtime.h>
#include <cuda_fp16.h>
#include <math.h>
#include <stdint.h>

// ---------------------------------------------------------------------------
// Problem constants
// ---------------------------------------------------------------------------
#define MB   4
#define SS   2048
#define DD   256
#define HH   8
#define KDD  256
#define FFD  512
#define MTOK (MB * SS)        // 8192
#define HKD  (HH * KDD)       // 2048
#define BH   (MB * HH)        // 32

// ---------------------------------------------------------------------------
// Static scratch (device .bss — no runtime allocation)
// ---------------------------------------------------------------------------
__device__ __align__(256) __half g_q16 [(long long)MTOK * HKD];     // [b,s,h,e]
__device__ __align__(256) __half g_k16 [(long long)MTOK * HKD];
__device__ __align__(256) __half g_v16 [(long long)MTOK * HKD];
__device__ __align__(256) __half g_vt16[(long long)BH * KDD * SS];  // [bh,e,s]
__device__ __align__(256) __half g_at16[(long long)MTOK * HKD];     // [b,s,h,e]
__device__ float g_ao[(long long)MTOK * DD];
__device__ float g_z [(long long)MTOK * DD];
__device__ __align__(256) __half g_z16 [(long long)MTOK * DD];
__device__ __align__(256) __half g_h16 [(long long)MTOK * FFD];
__device__ float g_f [(long long)MTOK * DD];
// pre-converted / pre-transposed inputs (all [N,K] fp16)
__device__ __align__(256) __half g_x16 [(long long)MTOK * DD];
__device__ __align__(256) __half g_wq16[(long long)HKD * DD];
__device__ __align__(256) __half g_wk16[(long long)HKD * DD];
__device__ __align__(256) __half g_wv16[(long long)HKD * DD];
__device__ __align__(256) __half g_wo16[(long long)DD * HKD];
__device__ __align__(256) __half g_w116[(long long)FFD * DD];
__device__ __align__(256) __half g_w216[(long long)DD * FFD];

// ---------------------------------------------------------------------------
// PTX helpers
// ---------------------------------------------------------------------------
#define CP_ASYNC16(saddr, gptr) \
    asm volatile("cp.async.cg.shared.global [%0], [%1], 16;" :: "r"(saddr), "l"(gptr))
#define CP_COMMIT()  asm volatile("cp.async.commit_group;" ::: "memory")
#define CP_WAIT_1()  asm volatile("cp.async.wait_group 1;" ::: "memory")
#define CP_WAIT_0()  asm volatile("cp.async.wait_group 0;" ::: "memory")

__device__ __forceinline__ uint32_t smem_u32(const void* p) {
    uint32_t a;
    asm("{ .reg .u64 t; cvta.to.shared.u64 t, %1; cvt.u32.u64 %0, t; }" : "=r"(a) : "l"(p));
    return a;
}

// fp16 MMA: D(f32) += A(f16,row) x B(f16,col), 16x8x16
__device__ __forceinline__ void mma_f16(
    float& c0, float& c1, float& c2, float& c3,
    uint32_t a0, uint32_t a1, uint32_t a2, uint32_t a3,
    uint32_t b0, uint32_t b1)
{
    asm volatile(
        "mma.sync.aligned.m16n8k16.row.col.f32.f16.f16.f32 "
        "{%0,%1,%2,%3}, {%4,%5,%6,%7}, {%8,%9}, {%0,%1,%2,%3};"
        : "+f"(c0), "+f"(c1), "+f"(c2), "+f"(c3)
        : "r"(a0), "r"(a1), "r"(a2), "r"(a3), "r"(b0), "r"(b1));
}

#define LDSM_X4(r0, r1, r2, r3, addr) \
    asm volatile("ldmatrix.sync.aligned.m8n8.x4.shared.b16 {%0,%1,%2,%3}, [%4];" \
                 : "=r"(r0), "=r"(r1), "=r"(r2), "=r"(r3) : "r"(addr))

__device__ __forceinline__ uint32_t packh2(float lo, float hi) {
    uint32_t u;
    asm("cvt.rn.f16x2.f32 %0, %1, %2;" : "=r"(u) : "f"(hi), "f"(lo));
    return u;
}

// ---------------------------------------------------------------------------
// TN fp16 tensor-core GEMM (unchanged from R10, proven bit-correct)
// ---------------------------------------------------------------------------
#define BKH 64
#define ROWW 36
#define OPW  (128 * ROWW)
#define STW  (2 * OPW)
#define HG_SMEM (2 * STW * 4)       // 73728 bytes

__global__ void __launch_bounds__(256)
hgemm(const __half* __restrict__ A, const __half* __restrict__ B,
      void* __restrict__ Cv, const float* __restrict__ bias,
      int K, int lda, int ldb, int ldc,
      int batch_div,
      long long sAo, long long sAi,
      long long sBo, long long sBi,
      long long sCo, long long sCi,
      float alpha, int relu, int outhalf)
{
    extern __shared__ uint32_t smw[];
    const uint32_t sbase = smem_u32(smw);

    const int z  = blockIdx.z;
    const int zo = z / batch_div;
    const int zi = z - zo * batch_div;
    A += zo * sAo + zi * sAi;
    B += zo * sBo + zi * sBi;

    const int tid  = threadIdx.x;
    const int lane = tid & 31;
    const int wrp  = tid >> 5;
    const int m0   = blockIdx.y * 128;
    const int n0   = blockIdx.x * 128;

    const int wm = (wrp & 1) * 64;
    const int wn = (wrp >> 1) * 32;
    const int g  = lane >> 2;
    const int tg = lane & 3;

    const __half* Ab = A + (long long)m0 * lda;
    const __half* Bb = B + (long long)n0 * ldb;

    float acc[4][4][4];
#pragma unroll
    for (int mi = 0; mi < 4; mi++)
#pragma unroll
        for (int ni = 0; ni < 4; ni++)
#pragma unroll
            for (int r = 0; r < 4; r++) acc[mi][ni][r] = 0.f;

    const int l15 = lane & 15;
    const int l7  = lane & 7;
    uint32_t aAddr[4], bAddr[2];
#pragma unroll
    for (int mi = 0; mi < 4; mi++)
        aAddr[mi] = sbase + ((wm + mi * 16 + l15) * ROWW + (lane >> 4) * 4) * 4;
#pragma unroll
    for (int p = 0; p < 2; p++)
        bAddr[p] = sbase + OPW * 4 +
                   ((wn + p * 16 + (lane >> 4) * 8 + l7) * ROWW +
                    ((lane >> 3) & 1) * 4) * 4;

    const int lrow = tid >> 3;
    const int lk8  = tid & 7;

    auto issue = [&](int st, int k0) {
        const uint32_t s0 = sbase + (st * STW) * 4;
#pragma unroll
        for (int i = 0; i < 4; i++) {
            const int row = lrow + i * 32;
            const uint32_t off = (row * ROWW + lk8 * 4) * 4;
            CP_ASYNC16(s0 + off,           Ab + (long long)row * lda + k0 + lk8 * 8);
            CP_ASYNC16(s0 + OPW * 4 + off, Bb + (long long)row * ldb + k0 + lk8 * 8);
        }
        CP_COMMIT();
    };

    const int T = K / BKH;
    issue(0, 0);

    for (int it = 0; it < T; it++) {
        const int st = it & 1;
        if (it + 1 < T) {
            issue(st ^ 1, (it + 1) * BKH);
            CP_WAIT_1();
        } else {
            CP_WAIT_0();
        }
        __syncthreads();

        const uint32_t sOff = (uint32_t)(st * STW) * 4;

#pragma unroll
        for (int ks = 0; ks < 4; ks++) {
            const uint32_t ko = sOff + ks * 32;
            uint32_t a[4][4];
#pragma unroll
            for (int mi = 0; mi < 4; mi++)
                LDSM_X4(a[mi][0], a[mi][1], a[mi][2], a[mi][3], aAddr[mi] + ko);
            uint32_t b[4][2];
#pragma unroll
            for (int p = 0; p < 2; p++)
                LDSM_X4(b[2 * p][0], b[2 * p][1], b[2 * p + 1][0], b[2 * p + 1][1],
                        bAddr[p] + ko);
#pragma unroll
            for (int mi = 0; mi < 4; mi++)
#pragma unroll
                for (int ni = 0; ni < 4; ni++)
                    mma_f16(acc[mi][ni][0], acc[mi][ni][1],
                            acc[mi][ni][2], acc[mi][ni][3],
                            a[mi][0], a[mi][1], a[mi][2], a[mi][3],
                            b[ni][0], b[ni][1]);
        }
        __syncthreads();
    }

    float*  Cf = (float*)Cv  + zo * sCo + zi * sCi;
    __half* Ch = (__half*)Cv + zo * sCo + zi * sCi;
#pragma unroll
    for (int mi = 0; mi < 4; mi++) {
        const int r0 = m0 + wm + mi * 16 + g;
#pragma unroll
        for (int ni = 0; ni < 4; ni++) {
            const int col = n0 + wn + ni * 8 + tg * 2;
            float v0 = acc[mi][ni][0], v1 = acc[mi][ni][1];
            float v2 = acc[mi][ni][2], v3 = acc[mi][ni][3];
            if (bias) {
                const float b0 = bias[col], b1 = bias[col + 1];
                v0 += b0; v1 += b1; v2 += b0; v3 += b1;
            }
            v0 *= alpha; v1 *= alpha; v2 *= alpha; v3 *= alpha;
            if (relu) {
                v0 = fmaxf(v0, 0.f); v1 = fmaxf(v1, 0.f);
                v2 = fmaxf(v2, 0.f); v3 = fmaxf(v3, 0.f);
            }
            if (outhalf) {
                *(__half2*)(Ch + (long long)r0 * ldc + col) =
                    __floats2half2_rn(v0, v1);
                *(__half2*)(Ch + (long long)(r0 + 8) * ldc + col) =
                    __floats2half2_rn(v2, v3);
            } else {
                *(float2*)(Cf + (long long)r0 * ldc + col)       = make_float2(v0, v1);
                *(float2*)(Cf + (long long)(r0 + 8) * ldc + col) = make_float2(v2, v3);
            }
        }
    }
}

// ---------------------------------------------------------------------------
// Fused flash attention: at = softmax(q k^T) v  per (b,h).
// CTA: 128 q-rows of one (b,h); warp w owns rows [w*16, w*16+16).
// K/V streamed in 64-key tiles, 2-stage cp.async. Online softmax, O in regs.
// q already scaled by 1/sqrt(KD). Inputs fp16: q,k [b,s,h,e]; vt [bh,e,s].
// ---------------------------------------------------------------------------
#define QROWB 528                    // 256 halves + 16B pad (33 x 16B, odd)
#define VROWB 144                    // 64 halves + 16B pad (9 x 16B, odd)
#define QBYT  (128 * QROWB)          // 67584
#define KBYT  (64 * QROWB)           // 33792
#define VBYT  (256 * VROWB)          // 36864
#define STBYT (KBYT + VBYT)          // 70656
#define FA_SMEM (QBYT + 2 * STBYT)   // 208896

__global__ void __launch_bounds__(256, 1)
fattn(const __half* __restrict__ q, const __half* __restrict__ k,
      const __half* __restrict__ vt, __half* __restrict__ o)
{
    extern __shared__ char fsm[];
    const uint32_t sb = smem_u32(fsm);

    const int tid = threadIdx.x, lane = tid & 31, w = tid >> 5;
    const int g = lane >> 2, tg = lane & 3;
    const int l15 = lane & 15, l7 = lane & 7;
    const int qt = blockIdx.x, bh = blockIdx.y;
    const int b = bh >> 3, h = bh & 7;
    const long long tokQ = (long long)b * SS + qt * 128;

    // ---- load Q tile (128 x 256 halves), once ----
#pragma unroll
    for (int i = 0; i < 16; i++) {
        const int c = tid + i * 256, row = c >> 5, col = c & 31;
        CP_ASYNC16(sb + row * QROWB + col * 16,
                   q + ((tokQ + row) * HH + h) * KDD + col * 8);
    }
    CP_COMMIT();

    auto loadKV = [&](int st, int kt) {
        const uint32_t kb = sb + QBYT + st * STBYT;
        const uint32_t vb = kb + KBYT;
#pragma unroll
        for (int i = 0; i < 8; i++) {
            const int c = tid + i * 256, row = c >> 5, col = c & 31;
            CP_ASYNC16(kb + row * QROWB + col * 16,
                       k + (((long long)b * SS + kt * 64 + row) * HH + h) * KDD + col * 8);
        }
#pragma unroll
        for (int i = 0; i < 8; i++) {
            const int c = tid + i * 256, d = c >> 3, kc = c & 7;
            CP_ASYNC16(vb + d * VROWB + kc * 16,
                       vt + ((long long)bh * KDD + d) * SS + kt * 64 + kc * 8);
        }
        CP_COMMIT();
    };

    loadKV(0, 0);

    float acc[32][4];                 // O: 32 d-tiles of 8, rows g / g+8
#pragma unroll
    for (int nd = 0; nd < 32; nd++)
#pragma unroll
        for (int r = 0; r < 4; r++) acc[nd][r] = 0.f;
    float m0 = -1e30f, m1 = -1e30f, l0 = 0.f, l1 = 0.f;

    const uint32_t qa = sb + (w * 16 + l15) * QROWB + (lane >> 4) * 16;

    for (int kt = 0; kt < 32; kt++) {
        const int st = kt & 1;
        if (kt + 1 < 32) { loadKV(st ^ 1, kt + 1); CP_WAIT_1(); }
        else             { CP_WAIT_0(); }
        __syncthreads();

        const uint32_t kb = sb + QBYT + st * STBYT;
        const uint32_t vb = kb + KBYT;
        const uint32_t ka = kb + ((lane >> 4) * 8 + l7) * QROWB + ((lane >> 3) & 1) * 16;
        const uint32_t va = vb + ((lane >> 4) * 8 + l7) * VROWB + ((lane >> 3) & 1) * 16;

        // ---- S = Qw (16 x 256) @ Ktile^T (64 x 256) ----
        float s[8][4];
#pragma unroll
        for (int ni = 0; ni < 8; ni++)
#pragma unroll
            for (int r = 0; r < 4; r++) s[ni][r] = 0.f;

#pragma unroll
        for (int kk = 0; kk < 16; kk++) {
            uint32_t a0, a1, a2, a3;
            LDSM_X4(a0, a1, a2, a3, qa + kk * 32);
#pragma unroll
            for (int p = 0; p < 4; p++) {
                uint32_t b0, b1, b2, b3;
                LDSM_X4(b0, b1, b2, b3, ka + p * 16 * QROWB + kk * 32);
                mma_f16(s[2 * p][0], s[2 * p][1], s[2 * p][2], s[2 * p][3],
                        a0, a1, a2, a3, b0, b1);
                mma_f16(s[2 * p + 1][0], s[2 * p + 1][1], s[2 * p + 1][2], s[2 * p + 1][3],
                        a0, a1, a2, a3, b2, b3);
            }
        }

        // ---- online softmax update (rows g and g+8, stats within 4 lanes) ----
        float r0 = -1e30f, r1 = -1e30f;
#pragma unroll
        for (int ni = 0; ni < 8; ni++) {
            r0 = fmaxf(r0, fmaxf(s[ni][0], s[ni][1]));
            r1 = fmaxf(r1, fmaxf(s[ni][2], s[ni][3]));
        }
        r0 = fmaxf(r0, __shfl_xor_sync(0xffffffffu, r0, 1));
        r0 = fmaxf(r0, __shfl_xor_sync(0xffffffffu, r0, 2));
        r1 = fmaxf(r1, __shfl_xor_sync(0xffffffffu, r1, 1));
        r1 = fmaxf(r1, __shfl_xor_sync(0xffffffffu, r1, 2));
        const float mn0 = fmaxf(m0, r0), mn1 = fmaxf(m1, r1);
        const float sc0 = __expf(m0 - mn0), sc1 = __expf(m1 - mn1);

        uint32_t afr[4][4];
        float ps0 = 0.f, ps1 = 0.f;
#pragma unroll
        for (int kk = 0; kk < 4; kk++) {
            const float p00 = __expf(s[2 * kk][0] - mn0);
            const float p01 = __expf(s[2 * kk][1] - mn0);
            const float p10 = __expf(s[2 * kk][2] - mn1);
            const float p11 = __expf(s[2 * kk][3] - mn1);
            const float p20 = __expf(s[2 * kk + 1][0] - mn0);
            const float p21 = __expf(s[2 * kk + 1][1] - mn0);
            const float p30 = __expf(s[2 * kk + 1][2] - mn1);
            const float p31 = __expf(s[2 * kk + 1][3] - mn1);
            ps0 += p00 + p01 + p20 + p21;
            ps1 += p10 + p11 + p30 + p31;
            afr[kk][0] = packh2(p00, p01);
            afr[kk][1] = packh2(p10, p11);
            afr[kk][2] = packh2(p20, p21);
            afr[kk][3] = packh2(p30, p31);
        }
        l0 = l0 * sc0 + ps0;
        l1 = l1 * sc1 + ps1;
#pragma unroll
        for (int nd = 0; nd < 32; nd++) {
            acc[nd][0] *= sc0; acc[nd][1] *= sc0;
            acc[nd][2] *= sc1; acc[nd][3] *= sc1;
        }
        m0 = mn0; m1 = mn1;

        // ---- O += P (16 x 64) @ Vtile (64 x 256) ----
#pragma unroll
        for (int kk = 0; kk < 4; kk++) {
#pragma unroll
            for (int p = 0; p < 16; p++) {
                uint32_t b0, b1, b2, b3;
                LDSM_X4(b0, b1, b2, b3, va + p * 16 * VROWB + kk * 32);
                mma_f16(acc[2 * p][0], acc[2 * p][1], acc[2 * p][2], acc[2 * p][3],
                        afr[kk][0], afr[kk][1], afr[kk][2], afr[kk][3], b0, b1);
                mma_f16(acc[2 * p + 1][0], acc[2 * p + 1][1],
                        acc[2 * p + 1][2], acc[2 * p + 1][3],
                        afr[kk][0], afr[kk][1], afr[kk][2], afr[kk][3], b2, b3);
            }
        }
        __syncthreads();     // all warps done reading stage st before next refill
    }

    // ---- finalize: divide by l, store fp16 [b,s,h,e] ----
    l0 += __shfl_xor_sync(0xffffffffu, l0, 1);
    l0 += __shfl_xor_sync(0xffffffffu, l0, 2);
    l1 += __shfl_xor_sync(0xffffffffu, l1, 1);
    l1 += __shfl_xor_sync(0xffffffffu, l1, 2);
    const float inv0 = 1.f / l0, inv1 = 1.f / l1;

    __half* o0 = o + ((tokQ + w * 16 + g) * HH + h) * KDD;
    __half* o1 = o + ((tokQ + w * 16 + g + 8) * HH + h) * KDD;
#pragma unroll
    for (int nd = 0; nd < 32; nd++) {
        const int col = nd * 8 + tg * 2;
        *(__half2*)(o0 + col) = __floats2half2_rn(acc[nd][0] * inv0, acc[nd][1] * inv0);
        *(__half2*)(o1 + col) = __floats2half2_rn(acc[nd][2] * inv1, acc[nd][3] * inv1);
    }
}

// ---------------------------------------------------------------------------
// fp32 -> fp16 elementwise (x)
// ---------------------------------------------------------------------------
__global__ void __launch_bounds__(256)
conv_h(const float* __restrict__ src, __half* __restrict__ dst, int n)
{
    int i = blockIdx.x * 256 + threadIdx.x;
    if (i < n) dst[i] = __float2half_rn(src[i]);
}

// src [K,N] fp32 -> dst [N,K] fp16 (weights). Dims multiples of 32.
__global__ void __launch_bounds__(256)
convT_h(const float* __restrict__ src, __half* __restrict__ dst, int Kd, int Nd)
{
    __shared__ float t[32][33];
    const int tx = threadIdx.x & 31, ty = threadIdx.x >> 5;
    const int k0 = blockIdx.x * 32, n0 = blockIdx.y * 32;
#pragma unroll
    for (int i = ty; i < 32; i += 8)
        t[i][tx] = src[(long long)(k0 + i) * Nd + n0 + tx];
    __syncthreads();
#pragma unroll
    for (int i = ty; i < 32; i += 8)
        dst[(long long)(n0 + i) * Kd + k0 + tx] = __float2half_rn(t[tx][i]);
}

// v[b,s,h,e] fp16 -> vt[bh,e,s] fp16
__global__ void __launch_bounds__(256)
vtrans_h(const __half* __restrict__ v, __half* __restrict__ vt)
{
    __shared__ __half t[32][33];
    const int tx = threadIdx.x & 31, ty = threadIdx.x >> 5;
    const int bh = blockIdx.z, b = bh >> 3, h = bh & 7;
    const int s0 = blockIdx.x * 32, e0 = blockIdx.y * 32;
#pragma unroll
    for (int i = ty; i < 32; i += 8)
        t[i][tx] = v[((long long)(b * SS + s0 + i) * HH + h) * KDD + e0 + tx];
    __syncthreads();
#pragma unroll
    for (int i = ty; i < 32; i += 8)
        vt[((long long)bh * KDD + e0 + i) * SS + s0 + tx] = t[tx][i];
}

// ---------------------------------------------------------------------------
// LayerNorm (+ residual). D = 256 = blockDim.
// ---------------------------------------------------------------------------
__global__ void __launch_bounds__(256)
ln_kernel(const float* __restrict__ a, const float* __restrict__ r,
          const float* __restrict__ g, const float* __restrict__ b,
          float* __restrict__ out, __half* __restrict__ out16, int add_before)
{
    const int t = threadIdx.x;
    const long long base = (long long)blockIdx.x * DD;
    const float av = a[base + t];
    const float rv = r[base + t];
    const float val = add_before ? (av + rv) : av;

    __shared__ float sh[256];
    sh[t] = val; __syncthreads();
    for (int st = 128; st; st >>= 1) {
        if (t < st) sh[t] += sh[t + st];
        __syncthreads();
    }
    const float mean = sh[0] * (1.f / 256.f);
    __syncthreads();

    const float d = val - mean;
    sh[t] = d * d; __syncthreads();
    for (int st = 128; st; st >>= 1) {
        if (t < st) sh[t] += sh[t + st];
        __syncthreads();
    }
    const float var = sh[0] * (1.f / 256.f);

    const float y = d * rsqrtf(var + 1e-3f) * g[t] + b[t];
    const float o = add_before ? y : (y + rv);
    out[base + t] = o;
    if (out16) out16[base + t] = __float2half_rn(o);
}

// ---------------------------------------------------------------------------
// Launch
// ---------------------------------------------------------------------------
extern "C" void kernel_launch(void* const* d_in, const int* in_sizes, int n_in,
                              void* d_out, int out_size)
{
    const float* x   = (const float*)d_in[0];
    const float* Wq  = (const float*)d_in[1];
    const float* bq  = (const float*)d_in[2];
    const float* Wk  = (const float*)d_in[3];
    const float* bk  = (const float*)d_in[4];
    const float* Wv  = (const float*)d_in[5];
    const float* bv  = (const float*)d_in[6];
    const float* Wo  = (const float*)d_in[7];
    const float* bo  = (const float*)d_in[8];
    const float* g1  = (const float*)d_in[9];
    const float* be1 = (const float*)d_in[10];
    const float* W1  = (const float*)d_in[11];
    const float* bb1 = (const float*)d_in[12];
    const float* W2  = (const float*)d_in[13];
    const float* bb2 = (const float*)d_in[14];
    const float* g2  = (const float*)d_in[15];
    const float* be2 = (const float*)d_in[16];
    float* out = (float*)d_out;

    __half *q16, *k16, *v16, *vt16, *at16, *z16, *h16;
    __half *x16, *wq16, *wk16, *wv16, *wo16, *w116, *w216;
    float *ao, *zz, *ff;
    cudaGetSymbolAddress((void**)&q16,  g_q16);
    cudaGetSymbolAddress((void**)&k16,  g_k16);
    cudaGetSymbolAddress((void**)&v16,  g_v16);
    cudaGetSymbolAddress((void**)&vt16, g_vt16);
    cudaGetSymbolAddress((void**)&at16, g_at16);
    cudaGetSymbolAddress((void**)&z16,  g_z16);
    cudaGetSymbolAddress((void**)&h16,  g_h16);
    cudaGetSymbolAddress((void**)&x16,  g_x16);
    cudaGetSymbolAddress((void**)&wq16, g_wq16);
    cudaGetSymbolAddress((void**)&wk16, g_wk16);
    cudaGetSymbolAddress((void**)&wv16, g_wv16);
    cudaGetSymbolAddress((void**)&wo16, g_wo16);
    cudaGetSymbolAddress((void**)&w116, g_w116);
    cudaGetSymbolAddress((void**)&w216, g_w216);
    cudaGetSymbolAddress((void**)&ao,   g_ao);
    cudaGetSymbolAddress((void**)&zz,   g_z);
    cudaGetSymbolAddress((void**)&ff,   g_f);

    cudaFuncSetAttribute(hgemm, cudaFuncAttributeMaxDynamicSharedMemorySize, HG_SMEM);
    cudaFuncSetAttribute(fattn, cudaFuncAttributeMaxDynamicSharedMemorySize, FA_SMEM);

    const dim3 blk(256);
    const float qscale = 1.0f / 16.0f;   // 1/sqrt(KD)

    // ---- prep: x -> fp16; weights -> [N,K] fp16 -----------------------------
    conv_h<<<(MTOK * DD) / 256, blk>>>(x, x16, MTOK * DD);
    convT_h<<<dim3(DD / 32, HKD / 32), blk>>>(Wq, wq16, DD, HKD);
    convT_h<<<dim3(DD / 32, HKD / 32), blk>>>(Wk, wk16, DD, HKD);
    convT_h<<<dim3(DD / 32, HKD / 32), blk>>>(Wv, wv16, DD, HKD);
    convT_h<<<dim3(HKD / 32, DD / 32), blk>>>(Wo, wo16, HKD, DD);
    convT_h<<<dim3(DD / 32, FFD / 32), blk>>>(W1, w116, DD, FFD);
    convT_h<<<dim3(FFD / 32, DD / 32), blk>>>(W2, w216, FFD, DD);

    // ---- Q/K/V projections (TN) -> [b,s,h,e] fp16 (q scaled) ----------------
    {
        dim3 grid(HKD / 128, MTOK / 128, 1);
        hgemm<<<grid, blk, HG_SMEM>>>(x16, wq16, q16, bq, DD, DD, DD, HKD,
                                      1, 0, 0, 0, 0, 0, 0, qscale, 0, 1);
        hgemm<<<grid, blk, HG_SMEM>>>(x16, wk16, k16, bk, DD, DD, DD, HKD,
                                      1, 0, 0, 0, 0, 0, 0, 1.f, 0, 1);
        hgemm<<<grid, blk, HG_SMEM>>>(x16, wv16, v16, bv, DD, DD, DD, HKD,
                                      1, 0, 0, 0, 0, 0, 0, 1.f, 0, 1);
    }

    // ---- vt[bh,e,s] ---------------------------------------------------------
    vtrans_h<<<dim3(SS / 32, KDD / 32, BH), blk>>>(v16, vt16);

    // ---- fused attention: at16 = softmax(q k^T) v ---------------------------
    fattn<<<dim3(SS / 128, BH), blk, FA_SMEM>>>(q16, k16, vt16, at16);

    // ---- output projection (TN) fp32 out ------------------------------------
    {
        dim3 grid(DD / 128, MTOK / 128, 1);
        hgemm<<<grid, blk, HG_SMEM>>>(at16, wo16, ao, bo, HKD, HKD, HKD, DD,
                                      1, 0, 0, 0, 0, 0, 0, 1.f, 0, 0);
    }

    // ---- z = LN(attn_out) + x (fp32 exact + fp16 copy) ----------------------
    ln_kernel<<<MTOK, blk>>>(ao, x, g1, be1, zz, z16, 0);

    // ---- FFN ----------------------------------------------------------------
    {
        dim3 grid(FFD / 128, MTOK / 128, 1);
        hgemm<<<grid, blk, HG_SMEM>>>(z16, w116, h16, bb1, DD, DD, DD, FFD,
                                      1, 0, 0, 0, 0, 0, 0, 1.f, 1, 1);
    }
    {
        dim3 grid(DD / 128, MTOK / 128, 1);
        hgemm<<<grid, blk, HG_SMEM>>>(h16, w216, ff, bb2, FFD, FFD, FFD, DD,
                                      1, 0, 0, 0, 0, 0, 0, 1.f, 0, 0);
    }

    // ---- out = LN(f + z) ----------------------------------------------------
    ln_kernel<<<MTOK, blk>>>(ff, zz, g2, be2, out, nullptr, 1);
}